// round 8
// baseline (speedup 1.0000x reference)
#include <cuda_runtime.h>
#include <cstdint>
#include <cstddef>

// Problem constants
#define NN 100000
#define EE 600000
#define DD 128

// ---------------- scratch ----------------
__device__ float g_Q   [(size_t)NN * DD];
__device__ float g_K   [(size_t)NN * DD];
__device__ float g_V   [(size_t)NN * DD];
__device__ float g_SKIP[(size_t)NN * DD];
__device__ float g_AGG [(size_t)NN * DD];
__device__ float g_H   [(size_t)NN * DD];
__device__ float g_den [(size_t)NN * 8];
__device__ int   g_is64;

// ---------------- tf32 helpers ----------------
__device__ __forceinline__ uint32_t f2tf32(float v) {
    uint32_t r;
    asm("cvt.rna.tf32.f32 %0, %1;" : "=r"(r) : "f"(v));
    return r;
}
__device__ __forceinline__ void mma_tf32(float& d0, float& d1, float& d2, float& d3,
                                         uint32_t a0, uint32_t a1, uint32_t a2, uint32_t a3,
                                         uint32_t b0, uint32_t b1) {
    asm volatile(
        "mma.sync.aligned.m16n8k8.row.col.f32.tf32.tf32.f32 "
        "{%0,%1,%2,%3}, {%4,%5,%6,%7}, {%8,%9}, {%0,%1,%2,%3};"
        : "+f"(d0), "+f"(d1), "+f"(d2), "+f"(d3)
        : "r"(a0), "r"(a1), "r"(a2), "r"(a3), "r"(b0), "r"(b1));
}

#define AS_STRIDE 132
#define WS_STRIDE 136
#define AS_ELEMS  (64 * AS_STRIDE)                 // proj/ffn A tile (64 rows)
#define WS_ELEMS  (128 * WS_STRIDE)
#define FFN_SMEM  ((AS_ELEMS + WS_ELEMS) * 4)      // 103424
#define GEMM_SMEM FFN_SMEM

// fused edge kernel: 32-edge tiles, double buffered
#define ET_ROWS   32
#define ET_ELEMS  (ET_ROWS * AS_STRIDE)            // 4224 floats = 16896 B
#define FUSED_SMEM (WS_ELEMS * 4 + 2 * ET_ELEMS * 4 + 2 * 64 * 4)  // 103936
#define TPC 16   // 32-edge tiles per CTA

__device__ __forceinline__ int load_idx(const void* p, long long i, int is64) {
    if (is64) return (int)((const long long*)p)[i];
    return ((const int*)p)[i];
}

// ---------------- node projection GEMM (Q,K,V,SKIP share staged x) — R6 proven ----------------
__global__ void __launch_bounds__(256, 2)
mma_gemm_kernel(const float* __restrict__ A, int M, int nw,
                const float* Wg0, const float* Wg1, const float* Wg2, const float* Wg3,
                const float* bg0, const float* bg1, const float* bg2, const float* bg3,
                float* og0, float* og1, float* og2, float* og3) {
    extern __shared__ uint32_t sm[];
    uint32_t* As = sm;
    uint32_t* Ws = sm + AS_ELEMS;

    int tid = threadIdx.x;
    int wid = tid >> 5;
    int lane = tid & 31;
    int row0 = blockIdx.x * 64;

    const float* Wp[4] = {Wg0, Wg1, Wg2, Wg3};
    const float* Bp[4] = {bg0, bg1, bg2, bg3};
    float*       Op[4] = {og0, og1, og2, og3};

#pragma unroll
    for (int it = 0; it < 8; it++) {
        int idx = it * 256 + tid;
        int r = idx >> 5, c4 = idx & 31;
        float4 v = make_float4(0.f, 0.f, 0.f, 0.f);
        if (row0 + r < M) v = ((const float4*)(A + (size_t)(row0 + r) * DD))[c4];
        uint4 t = make_uint4(f2tf32(v.x), f2tf32(v.y), f2tf32(v.z), f2tf32(v.w));
        *(uint4*)&As[r * AS_STRIDE + c4 * 4] = t;
    }

    int wr = wid & 1, wc = wid >> 1;
    int qid = lane >> 2, qln = lane & 3;

    for (int w = 0; w < nw; w++) {
        __syncthreads();
        const float* Wgp = Wp[w];
#pragma unroll
        for (int it = 0; it < 16; it++) {
            int idx = it * 256 + tid;
            int k = idx >> 5, c4 = idx & 31;
            float4 v = ((const float4*)(Wgp + (size_t)k * DD))[c4];
            uint4 t = make_uint4(f2tf32(v.x), f2tf32(v.y), f2tf32(v.z), f2tf32(v.w));
            *(uint4*)&Ws[k * WS_STRIDE + c4 * 4] = t;
        }
        __syncthreads();

        float acc[2][4][4];
#pragma unroll
        for (int mt = 0; mt < 2; mt++)
#pragma unroll
            for (int nt = 0; nt < 4; nt++)
#pragma unroll
                for (int j = 0; j < 4; j++) acc[mt][nt][j] = 0.f;

#pragma unroll
        for (int ks = 0; ks < 16; ks++) {
            int k0 = ks * 8;
            uint32_t af[2][4];
#pragma unroll
            for (int mt = 0; mt < 2; mt++) {
                int r = wr * 32 + mt * 16 + qid;
                const uint32_t* ap = &As[r * AS_STRIDE + k0 + qln];
                af[mt][0] = ap[0];
                af[mt][2] = ap[4];
                af[mt][1] = ap[8 * AS_STRIDE];
                af[mt][3] = ap[8 * AS_STRIDE + 4];
            }
#pragma unroll
            for (int nt = 0; nt < 4; nt++) {
                int n0 = wc * 32 + nt * 8;
                uint32_t b0 = Ws[(k0 + qln) * WS_STRIDE + n0 + qid];
                uint32_t b1 = Ws[(k0 + 4 + qln) * WS_STRIDE + n0 + qid];
#pragma unroll
                for (int mt = 0; mt < 2; mt++)
                    mma_tf32(acc[mt][nt][0], acc[mt][nt][1], acc[mt][nt][2], acc[mt][nt][3],
                             af[mt][0], af[mt][1], af[mt][2], af[mt][3], b0, b1);
            }
        }

        const float* bias = Bp[w];
        float* outp = Op[w];
#pragma unroll
        for (int nt = 0; nt < 4; nt++) {
            int col = wc * 32 + nt * 8 + qln * 2;
            float b0v = bias[col], b1v = bias[col + 1];
#pragma unroll
            for (int mt = 0; mt < 2; mt++) {
                int r = row0 + wr * 32 + mt * 16 + qid;
                if (r < M)
                    *(float2*)&outp[(size_t)r * DD + col] =
                        make_float2(acc[mt][nt][0] + b0v, acc[mt][nt][1] + b1v);
                if (r + 8 < M)
                    *(float2*)&outp[(size_t)(r + 8) * DD + col] =
                        make_float2(acc[mt][nt][2] + b0v, acc[mt][nt][3] + b1v);
            }
        }
    }
}

// ---------------- FUSED pipelined: edge GEMM + attention ----------------
// 32-edge tiles, cp.async double-buffered EA staging (raw f32), tf32 cvt at
// fragment load. Warp layout: 8 warps each compute 32 rows x 16 cols.
__global__ void __launch_bounds__(256, 2)
fused_edge_kernel(const float* __restrict__ EA, const float* __restrict__ We,
                  const float* __restrict__ Q, const float* __restrict__ K,
                  const float* __restrict__ V, const void* __restrict__ eidx,
                  int E, float* __restrict__ denom, float* __restrict__ AGG) {
    extern __shared__ uint32_t sm[];
    uint32_t* Ws = sm;                                  // [128][WS_STRIDE] tf32
    float* Asb[2];
    Asb[0] = (float*)(sm + WS_ELEMS);
    Asb[1] = Asb[0] + ET_ELEMS;
    int* ssrc = (int*)(Asb[1] + ET_ELEMS);              // [2][32]
    int* sdst = ssrc + 64;                              // [2][32]

    int tid = threadIdx.x;
    int wid = tid >> 5;
    int lane = tid & 31;
    int is64 = g_is64;

    // stage We (tf32) once
#pragma unroll
    for (int it = 0; it < 16; it++) {
        int idx = it * 256 + tid;
        int k = idx >> 5, c4 = idx & 31;
        float4 v = ((const float4*)(We + (size_t)k * DD))[c4];
        uint4 t = make_uint4(f2tf32(v.x), f2tf32(v.y), f2tf32(v.z), f2tf32(v.w));
        *(uint4*)&Ws[k * WS_STRIDE + c4 * 4] = t;
    }

    int qid = lane >> 2, qln = lane & 3;
    int wc = wid;          // 16-col group per warp

    int ntiles = (E + ET_ROWS - 1) / ET_ROWS;
    int tbeg = blockIdx.x * TPC;
    int tend = tbeg + TPC;
    if (tend > ntiles) tend = ntiles;
    if (tbeg >= tend) return;

    // ---- stage helper inlined: prologue stage tile tbeg into buf 0 ----
    {
        int e0 = tbeg * ET_ROWS;
#pragma unroll
        for (int it = 0; it < 4; it++) {
            int idx = it * 256 + tid;
            int r = idx >> 5, c = idx & 31;
            float* dstp = &Asb[0][r * AS_STRIDE + c * 4];
            if (e0 + r < E) {
                uint32_t da = (uint32_t)__cvta_generic_to_shared(dstp);
                const float* srcp = EA + (size_t)(e0 + r) * DD + c * 4;
                asm volatile("cp.async.ca.shared.global [%0], [%1], 16;"
                             :: "r"(da), "l"(srcp) : "memory");
            } else {
                *(float4*)dstp = make_float4(0.f, 0.f, 0.f, 0.f);
            }
        }
        if (tid < 32) {
            int ok = (e0 + tid) < E;
            ssrc[tid] = ok ? load_idx(eidx, (long long)(e0 + tid), is64) : 0;
            sdst[tid] = ok ? load_idx(eidx, (long long)E + (e0 + tid), is64) : 0;
        }
        asm volatile("cp.async.commit_group;" ::: "memory");
    }

    int b = 0;
    for (int t = tbeg; t < tend; t++, b ^= 1) {
        asm volatile("cp.async.wait_group 0;" ::: "memory");
        __syncthreads();   // buf b ready; We staged (1st iter); prev attention done

        // issue stage of next tile into buf b^1 (proceeds during MMA+attention)
        if (t + 1 < tend) {
            int e0n = (t + 1) * ET_ROWS;
            float* dstb = Asb[b ^ 1];
#pragma unroll
            for (int it = 0; it < 4; it++) {
                int idx = it * 256 + tid;
                int r = idx >> 5, c = idx & 31;
                float* dstp = &dstb[r * AS_STRIDE + c * 4];
                if (e0n + r < E) {
                    uint32_t da = (uint32_t)__cvta_generic_to_shared(dstp);
                    const float* srcp = EA + (size_t)(e0n + r) * DD + c * 4;
                    asm volatile("cp.async.ca.shared.global [%0], [%1], 16;"
                                 :: "r"(da), "l"(srcp) : "memory");
                } else {
                    *(float4*)dstp = make_float4(0.f, 0.f, 0.f, 0.f);
                }
            }
            if (tid < 32) {
                int ok = (e0n + tid) < E;
                ssrc[(b ^ 1) * 32 + tid] =
                    ok ? load_idx(eidx, (long long)(e0n + tid), is64) : 0;
                sdst[(b ^ 1) * 32 + tid] =
                    ok ? load_idx(eidx, (long long)E + (e0n + tid), is64) : 0;
            }
            asm volatile("cp.async.commit_group;" ::: "memory");
        }

        // ---- MMA: Ef[32,128] = EA_tile @ We; this warp: rows 0..31, cols wc*16..+16
        const float* Af = Asb[b];
        float acc[2][2][4];
#pragma unroll
        for (int mt = 0; mt < 2; mt++)
#pragma unroll
            for (int nt = 0; nt < 2; nt++)
#pragma unroll
                for (int j = 0; j < 4; j++) acc[mt][nt][j] = 0.f;

#pragma unroll
        for (int ks = 0; ks < 16; ks++) {
            int k0 = ks * 8;
            uint32_t af[2][4];
#pragma unroll
            for (int mt = 0; mt < 2; mt++) {
                int r = mt * 16 + qid;
                const float* ap = &Af[r * AS_STRIDE + k0 + qln];
                af[mt][0] = f2tf32(ap[0]);
                af[mt][2] = f2tf32(ap[4]);
                af[mt][1] = f2tf32(ap[8 * AS_STRIDE]);
                af[mt][3] = f2tf32(ap[8 * AS_STRIDE + 4]);
            }
#pragma unroll
            for (int nt = 0; nt < 2; nt++) {
                int n0 = wc * 16 + nt * 8;
                uint32_t b0 = Ws[(k0 + qln) * WS_STRIDE + n0 + qid];
                uint32_t b1 = Ws[(k0 + 4 + qln) * WS_STRIDE + n0 + qid];
#pragma unroll
                for (int mt = 0; mt < 2; mt++)
                    mma_tf32(acc[mt][nt][0], acc[mt][nt][1], acc[mt][nt][2], acc[mt][nt][3],
                             af[mt][0], af[mt][1], af[mt][2], af[mt][3], b0, b1);
            }
        }
        __syncthreads();   // all warps done reading Af

        // Ef tile -> smem (overwrite buf b)
        float* Es = Asb[b];
#pragma unroll
        for (int nt = 0; nt < 2; nt++) {
            int col = wc * 16 + nt * 8 + qln * 2;
#pragma unroll
            for (int mt = 0; mt < 2; mt++) {
                int r = mt * 16 + qid;
                *(float2*)&Es[r * AS_STRIDE + col] =
                    make_float2(acc[mt][nt][0], acc[mt][nt][1]);
                *(float2*)&Es[(r + 8) * AS_STRIDE + col] =
                    make_float2(acc[mt][nt][2], acc[mt][nt][3]);
            }
        }
        __syncthreads();

        // ---- attention: warp wid handles edges 4*wid .. +3 of this tile
        int e0 = t * ET_ROWS;
        const int* sr = &ssrc[b * 32];
        const int* sd = &sdst[b * 32];
#pragma unroll
        for (int i = 0; i < 4; i++) {
            int le = wid * 4 + i;
            bool ok = (e0 + le) < E;
            int src = sr[le], dst = sd[le];

            float4 e4 = *(const float4*)&Es[le * AS_STRIDE + lane * 4];
            float4 q4 = *(const float4*)&Q[(size_t)dst * DD + lane * 4];
            float4 k4 = *(const float4*)&K[(size_t)src * DD + lane * 4];
            float4 v4 = *(const float4*)&V[(size_t)src * DD + lane * 4];

            float p = q4.x * (k4.x + e4.x) + q4.y * (k4.y + e4.y) +
                      q4.z * (k4.z + e4.z) + q4.w * (k4.w + e4.w);
            p += __shfl_xor_sync(0xffffffffu, p, 1);
            p += __shfl_xor_sync(0xffffffffu, p, 2);

            float ex = expf(p * 0.25f);
            if (ok) {
                if ((lane & 3) == 0)
                    atomicAdd(&denom[(size_t)dst * 8 + (lane >> 2)], ex);
                float m0 = ex * (v4.x + e4.x);
                float m1 = ex * (v4.y + e4.y);
                float m2 = ex * (v4.z + e4.z);
                float m3 = ex * (v4.w + e4.w);
                float* o = &AGG[(size_t)dst * DD + lane * 4];
                asm volatile("red.global.add.v4.f32 [%0], {%1,%2,%3,%4};"
                             :: "l"(o), "f"(m0), "f"(m1), "f"(m2), "f"(m3) : "memory");
            }
        }
        // no sync needed: buf b is next written by stage at t+2, which is
        // preceded by the loop-top __syncthreads of t+1 and t+2.
    }
}

// ---------------- FUSED FFN: out = H + LN(silu(H@W1+b1)@W2 + b2) — R6 proven ----------------
__global__ void __launch_bounds__(256, 2)
ffn_kernel(const float* __restrict__ H,
           const float* __restrict__ W1, const float* __restrict__ b1,
           const float* __restrict__ W2, const float* __restrict__ b2,
           const float* __restrict__ g, const float* __restrict__ be,
           float* __restrict__ outp, int M) {
    extern __shared__ uint32_t sm[];
    uint32_t* As = sm;
    uint32_t* Ws = sm + AS_ELEMS;

    int tid = threadIdx.x;
    int wid = tid >> 5;
    int lane = tid & 31;
    int row0 = blockIdx.x * 64;

#pragma unroll
    for (int it = 0; it < 8; it++) {
        int idx = it * 256 + tid;
        int r = idx >> 5, c4 = idx & 31;
        float4 v = make_float4(0.f, 0.f, 0.f, 0.f);
        if (row0 + r < M) v = ((const float4*)(H + (size_t)(row0 + r) * DD))[c4];
        uint4 t = make_uint4(f2tf32(v.x), f2tf32(v.y), f2tf32(v.z), f2tf32(v.w));
        *(uint4*)&As[r * AS_STRIDE + c4 * 4] = t;
    }
#pragma unroll
    for (int it = 0; it < 16; it++) {
        int idx = it * 256 + tid;
        int k = idx >> 5, c4 = idx & 31;
        float4 v = ((const float4*)(W1 + (size_t)k * DD))[c4];
        uint4 t = make_uint4(f2tf32(v.x), f2tf32(v.y), f2tf32(v.z), f2tf32(v.w));
        *(uint4*)&Ws[k * WS_STRIDE + c4 * 4] = t;
    }
    __syncthreads();

    int wr = wid & 1, wc = wid >> 1;
    int qid = lane >> 2, qln = lane & 3;

    float acc[2][4][4];
#pragma unroll
    for (int mt = 0; mt < 2; mt++)
#pragma unroll
        for (int nt = 0; nt < 4; nt++)
#pragma unroll
            for (int j = 0; j < 4; j++) acc[mt][nt][j] = 0.f;

#pragma unroll
    for (int ks = 0; ks < 16; ks++) {
        int k0 = ks * 8;
        uint32_t af[2][4];
#pragma unroll
        for (int mt = 0; mt < 2; mt++) {
            int r = wr * 32 + mt * 16 + qid;
            const uint32_t* ap = &As[r * AS_STRIDE + k0 + qln];
            af[mt][0] = ap[0];
            af[mt][2] = ap[4];
            af[mt][1] = ap[8 * AS_STRIDE];
            af[mt][3] = ap[8 * AS_STRIDE + 4];
        }
#pragma unroll
        for (int nt = 0; nt < 4; nt++) {
            int n0 = wc * 32 + nt * 8;
            uint32_t b0 = Ws[(k0 + qln) * WS_STRIDE + n0 + qid];
            uint32_t b1v = Ws[(k0 + 4 + qln) * WS_STRIDE + n0 + qid];
#pragma unroll
            for (int mt = 0; mt < 2; mt++)
                mma_tf32(acc[mt][nt][0], acc[mt][nt][1], acc[mt][nt][2], acc[mt][nt][3],
                         af[mt][0], af[mt][1], af[mt][2], af[mt][3], b0, b1v);
        }
    }
    __syncthreads();

#pragma unroll
    for (int nt = 0; nt < 4; nt++) {
        int col = wc * 32 + nt * 8 + qln * 2;
        float c0 = b1[col], c1 = b1[col + 1];
#pragma unroll
        for (int mt = 0; mt < 2; mt++) {
            int r = wr * 32 + mt * 16 + qid;
            float o0 = acc[mt][nt][0] + c0;
            float o1 = acc[mt][nt][1] + c1;
            float o2 = acc[mt][nt][2] + c0;
            float o3 = acc[mt][nt][3] + c1;
            o0 = o0 / (1.f + expf(-o0));
            o1 = o1 / (1.f + expf(-o1));
            o2 = o2 / (1.f + expf(-o2));
            o3 = o3 / (1.f + expf(-o3));
            As[r * AS_STRIDE + col]           = f2tf32(o0);
            As[r * AS_STRIDE + col + 1]       = f2tf32(o1);
            As[(r + 8) * AS_STRIDE + col]     = f2tf32(o2);
            As[(r + 8) * AS_STRIDE + col + 1] = f2tf32(o3);
        }
    }
#pragma unroll
    for (int it = 0; it < 16; it++) {
        int idx = it * 256 + tid;
        int k = idx >> 5, c4 = idx & 31;
        float4 v = ((const float4*)(W2 + (size_t)k * DD))[c4];
        uint4 t = make_uint4(f2tf32(v.x), f2tf32(v.y), f2tf32(v.z), f2tf32(v.w));
        *(uint4*)&Ws[k * WS_STRIDE + c4 * 4] = t;
    }
    __syncthreads();

#pragma unroll
    for (int mt = 0; mt < 2; mt++)
#pragma unroll
        for (int nt = 0; nt < 4; nt++)
#pragma unroll
            for (int j = 0; j < 4; j++) acc[mt][nt][j] = 0.f;

#pragma unroll
    for (int ks = 0; ks < 16; ks++) {
        int k0 = ks * 8;
        uint32_t af[2][4];
#pragma unroll
        for (int mt = 0; mt < 2; mt++) {
            int r = wr * 32 + mt * 16 + qid;
            const uint32_t* ap = &As[r * AS_STRIDE + k0 + qln];
            af[mt][0] = ap[0];
            af[mt][2] = ap[4];
            af[mt][1] = ap[8 * AS_STRIDE];
            af[mt][3] = ap[8 * AS_STRIDE + 4];
        }
#pragma unroll
        for (int nt = 0; nt < 4; nt++) {
            int n0 = wc * 32 + nt * 8;
            uint32_t b0 = Ws[(k0 + qln) * WS_STRIDE + n0 + qid];
            uint32_t b1v = Ws[(k0 + 4 + qln) * WS_STRIDE + n0 + qid];
#pragma unroll
            for (int mt = 0; mt < 2; mt++)
                mma_tf32(acc[mt][nt][0], acc[mt][nt][1], acc[mt][nt][2], acc[mt][nt][3],
                         af[mt][0], af[mt][1], af[mt][2], af[mt][3], b0, b1v);
        }
    }
    __syncthreads();

    float* Es = (float*)Ws;
#pragma unroll
    for (int nt = 0; nt < 4; nt++) {
        int col = wc * 32 + nt * 8 + qln * 2;
        float c0 = b2[col], c1 = b2[col + 1];
#pragma unroll
        for (int mt = 0; mt < 2; mt++) {
            int r = wr * 32 + mt * 16 + qid;
            *(float2*)&Es[r * AS_STRIDE + col] =
                make_float2(acc[mt][nt][0] + c0, acc[mt][nt][1] + c1);
            *(float2*)&Es[(r + 8) * AS_STRIDE + col] =
                make_float2(acc[mt][nt][2] + c0, acc[mt][nt][3] + c1);
        }
    }
    __syncthreads();

#pragma unroll
    for (int i = 0; i < 8; i++) {
        int r = wid * 8 + i;
        float4 o = *(float4*)&Es[r * AS_STRIDE + lane * 4];

        float sum = o.x + o.y + o.z + o.w;
#pragma unroll
        for (int off = 16; off >= 1; off >>= 1)
            sum += __shfl_xor_sync(0xffffffffu, sum, off);
        float mu = sum * (1.0f / 128.0f);

        float dx = o.x - mu, dy = o.y - mu, dz = o.z - mu, dw = o.w - mu;
        float ss = dx * dx + dy * dy + dz * dz + dw * dw;
#pragma unroll
        for (int off = 16; off >= 1; off >>= 1)
            ss += __shfl_xor_sync(0xffffffffu, ss, off);
        float rs = rsqrtf(ss * (1.0f / 128.0f) + 1e-5f);

        if (row0 + r < M) {
            float4 gg = *(const float4*)&g[lane * 4];
            float4 bb = *(const float4*)&be[lane * 4];
            float4 hh = *(const float4*)&H[(size_t)(row0 + r) * DD + lane * 4];
            float4 rr;
            rr.x = hh.x + dx * rs * gg.x + bb.x;
            rr.y = hh.y + dy * rs * gg.y + bb.y;
            rr.z = hh.z + dz * rs * gg.z + bb.z;
            rr.w = hh.w + dw * rs * gg.w + bb.w;
            *(float4*)&outp[(size_t)(row0 + r) * DD + lane * 4] = rr;
        }
    }
}

// ---------------- edge index dtype detection ----------------
__global__ void detect_idx_kernel(const long long* __restrict__ p, int E, int N) {
    if (threadIdx.x == 0 && blockIdx.x == 0) {
        int ok64 = 1;
        int n = (E < 64) ? E : 64;
        for (int i = 0; i < n; i++) {
            long long v = p[i];
            if (v < 0 || v >= (long long)N) { ok64 = 0; break; }
        }
        g_is64 = ok64;
    }
}

// ---------------- zero accumulators ----------------
__global__ void zero_kernel(float* __restrict__ a, size_t na,
                            float* __restrict__ b, size_t nb) {
    size_t i = (size_t)blockIdx.x * blockDim.x + threadIdx.x;
    size_t stride = (size_t)gridDim.x * blockDim.x;
    for (size_t j = i; j < na; j += stride) a[j] = 0.0f;
    for (size_t j = i; j < nb; j += stride) b[j] = 0.0f;
}

// ---------------- h = x + LN(AGG/den + SKIP) ----------------
__global__ void postln1_kernel(const float* __restrict__ x, const float* __restrict__ AGG,
                               const float* __restrict__ SKIP, const float* __restrict__ den,
                               const float* __restrict__ g, const float* __restrict__ b,
                               float* __restrict__ outp, int M) {
    long long gw = ((long long)blockIdx.x * blockDim.x + threadIdx.x) >> 5;
    int lane = threadIdx.x & 31;
    if (gw >= M) return;

    float dh = den[(size_t)gw * 8 + (lane >> 2)];
    float inv = 1.0f / (dh + 1e-16f);

    float4 o = *(const float4*)&AGG[(size_t)gw * DD + lane * 4];
    float4 s = *(const float4*)&SKIP[(size_t)gw * DD + lane * 4];
    o.x = o.x * inv + s.x;
    o.y = o.y * inv + s.y;
    o.z = o.z * inv + s.z;
    o.w = o.w * inv + s.w;

    float sum = o.x + o.y + o.z + o.w;
#pragma unroll
    for (int off = 16; off >= 1; off >>= 1) sum += __shfl_xor_sync(0xffffffffu, sum, off);
    float mu = sum * (1.0f / 128.0f);

    float dx = o.x - mu, dy = o.y - mu, dz = o.z - mu, dw = o.w - mu;
    float ss = dx * dx + dy * dy + dz * dz + dw * dw;
#pragma unroll
    for (int off = 16; off >= 1; off >>= 1) ss += __shfl_xor_sync(0xffffffffu, ss, off);
    float rs = rsqrtf(ss * (1.0f / 128.0f) + 1e-5f);

    float4 gg = *(const float4*)&g[lane * 4];
    float4 bb = *(const float4*)&b[lane * 4];
    float4 xx = *(const float4*)&x[(size_t)gw * DD + lane * 4];

    float4 r;
    r.x = xx.x + dx * rs * gg.x + bb.x;
    r.y = xx.y + dy * rs * gg.y + bb.y;
    r.z = xx.z + dz * rs * gg.z + bb.z;
    r.w = xx.w + dw * rs * gg.w + bb.w;
    *(float4*)&outp[(size_t)gw * DD + lane * 4] = r;
}

// ---------------- launch ----------------
extern "C" void kernel_launch(void* const* d_in, const int* in_sizes, int n_in,
                              void* d_out, int out_size) {
    const void*  eidx      = d_in[0];
    const float* x         = (const float*)d_in[1];
    const float* edge_attr = (const float*)d_in[2];
    const float* Wq = (const float*)d_in[3],  *bq = (const float*)d_in[4];
    const float* Wk = (const float*)d_in[5],  *bk = (const float*)d_in[6];
    const float* Wv = (const float*)d_in[7],  *bv = (const float*)d_in[8];
    const float* We = (const float*)d_in[9];
    const float* Wskip = (const float*)d_in[10], *bskip = (const float*)d_in[11];
    const float* W1 = (const float*)d_in[12], *b1 = (const float*)d_in[13];
    const float* W2 = (const float*)d_in[14], *b2 = (const float*)d_in[15];
    const float* g1 = (const float*)d_in[16], *be1 = (const float*)d_in[17];
    const float* g2 = (const float*)d_in[18], *be2 = (const float*)d_in[19];
    float* out = (float*)d_out;

    int N = in_sizes[1] / DD;   // 100000
    int E = in_sizes[2] / DD;   // 600000

    float *pQ, *pK, *pV, *pSK, *pAGG, *pH, *pDen;
    cudaGetSymbolAddress((void**)&pQ,   g_Q);
    cudaGetSymbolAddress((void**)&pK,   g_K);
    cudaGetSymbolAddress((void**)&pV,   g_V);
    cudaGetSymbolAddress((void**)&pSK,  g_SKIP);
    cudaGetSymbolAddress((void**)&pAGG, g_AGG);
    cudaGetSymbolAddress((void**)&pH,   g_H);
    cudaGetSymbolAddress((void**)&pDen, g_den);

    cudaFuncSetAttribute(mma_gemm_kernel, cudaFuncAttributeMaxDynamicSharedMemorySize,
                         GEMM_SMEM);
    cudaFuncSetAttribute(fused_edge_kernel, cudaFuncAttributeMaxDynamicSharedMemorySize,
                         FUSED_SMEM);
    cudaFuncSetAttribute(ffn_kernel, cudaFuncAttributeMaxDynamicSharedMemorySize,
                         FFN_SMEM);

    detect_idx_kernel<<<1, 32>>>((const long long*)eidx, E, N);
    zero_kernel<<<1024, 256>>>(pDen, (size_t)N * 8, pAGG, (size_t)N * DD);

    // node projections
    int nb_node = (N + 63) / 64;
    mma_gemm_kernel<<<nb_node, 256, GEMM_SMEM>>>(x, N, 4,
        Wq, Wk, Wv, Wskip, bq, bk, bv, bskip, pQ, pK, pV, pSK);

    // fused pipelined edge GEMM + attention
    int ntiles = (E + ET_ROWS - 1) / ET_ROWS;
    int nb_fused = (ntiles + TPC - 1) / TPC;
    fused_edge_kernel<<<nb_fused, 256, FUSED_SMEM>>>(edge_attr, We, pQ, pK, pV,
                                                     eidx, E, pDen, pAGG);

    // h = x + LN(AGG/den + skip)
    int nbw = (N + 7) / 8;
    postln1_kernel<<<nbw, 256>>>(x, pAGG, pSK, pDen, g1, be1, pH, N);

    // fused FFN + final LN + residual -> out
    ffn_kernel<<<nb_node, 256, FFN_SMEM>>>(pH, W1, b1, W2, b2, g2, be2, out, N);
}

// round 9
// speedup vs baseline: 1.2338x; 1.2338x over previous
#include <cuda_runtime.h>
#include <cstdint>
#include <cstddef>

// Problem constants
#define NN 100000
#define EE 600000
#define DD 128

// ---------------- scratch ----------------
__device__ float g_Q   [(size_t)NN * DD];
__device__ float g_K   [(size_t)NN * DD];
__device__ float g_V   [(size_t)NN * DD];
__device__ float g_SKIP[(size_t)NN * DD];
__device__ float g_AGG [(size_t)NN * DD];
__device__ float g_H   [(size_t)NN * DD];
__device__ float g_den [(size_t)NN * 8];
__device__ int   g_is64;

// ---------------- tf32 helpers ----------------
__device__ __forceinline__ uint32_t f2tf32(float v) {
    uint32_t r;
    asm("cvt.rna.tf32.f32 %0, %1;" : "=r"(r) : "f"(v));
    return r;
}
__device__ __forceinline__ void mma_tf32(float& d0, float& d1, float& d2, float& d3,
                                         uint32_t a0, uint32_t a1, uint32_t a2, uint32_t a3,
                                         uint32_t b0, uint32_t b1) {
    asm volatile(
        "mma.sync.aligned.m16n8k8.row.col.f32.tf32.tf32.f32 "
        "{%0,%1,%2,%3}, {%4,%5,%6,%7}, {%8,%9}, {%0,%1,%2,%3};"
        : "+f"(d0), "+f"(d1), "+f"(d2), "+f"(d3)
        : "r"(a0), "r"(a1), "r"(a2), "r"(a3), "r"(b0), "r"(b1));
}

#define AS_STRIDE 132
#define WS_STRIDE 136
#define AS_ELEMS  (64 * AS_STRIDE)                 // 8448
#define WS_ELEMS  (128 * WS_STRIDE)                // 17408
#define GEMM_SMEM ((AS_ELEMS + WS_ELEMS) * 4)      // 103424 -> 2 CTAs/SM
#define FFN_SMEM  GEMM_SMEM
#define FUSED_SMEM (GEMM_SMEM + 64 * 2 * 4)

#define TPC 8   // 64-edge tiles per CTA in fused edge kernel

__device__ __forceinline__ int load_idx(const void* p, long long i, int is64) {
    if (is64) return (int)((const long long*)p)[i];
    return ((const int*)p)[i];
}

// ---------------- node projection GEMM (Q,K,V,SKIP share staged x) ----------------
__global__ void __launch_bounds__(256, 2)
mma_gemm_kernel(const float* __restrict__ A, int M, int nw,
                const float* Wg0, const float* Wg1, const float* Wg2, const float* Wg3,
                const float* bg0, const float* bg1, const float* bg2, const float* bg3,
                float* og0, float* og1, float* og2, float* og3) {
    extern __shared__ uint32_t sm[];
    uint32_t* As = sm;
    uint32_t* Ws = sm + AS_ELEMS;

    int tid = threadIdx.x;
    int wid = tid >> 5;
    int lane = tid & 31;
    int row0 = blockIdx.x * 64;

    const float* Wp[4] = {Wg0, Wg1, Wg2, Wg3};
    const float* Bp[4] = {bg0, bg1, bg2, bg3};
    float*       Op[4] = {og0, og1, og2, og3};

#pragma unroll
    for (int it = 0; it < 8; it++) {
        int idx = it * 256 + tid;
        int r = idx >> 5, c4 = idx & 31;
        float4 v = make_float4(0.f, 0.f, 0.f, 0.f);
        if (row0 + r < M) v = ((const float4*)(A + (size_t)(row0 + r) * DD))[c4];
        uint4 t = make_uint4(f2tf32(v.x), f2tf32(v.y), f2tf32(v.z), f2tf32(v.w));
        *(uint4*)&As[r * AS_STRIDE + c4 * 4] = t;
    }

    int wr = wid & 1, wc = wid >> 1;
    int qid = lane >> 2, qln = lane & 3;

    for (int w = 0; w < nw; w++) {
        __syncthreads();
        const float* Wgp = Wp[w];
#pragma unroll
        for (int it = 0; it < 16; it++) {
            int idx = it * 256 + tid;
            int k = idx >> 5, c4 = idx & 31;
            float4 v = ((const float4*)(Wgp + (size_t)k * DD))[c4];
            uint4 t = make_uint4(f2tf32(v.x), f2tf32(v.y), f2tf32(v.z), f2tf32(v.w));
            *(uint4*)&Ws[k * WS_STRIDE + c4 * 4] = t;
        }
        __syncthreads();

        float acc[2][4][4];
#pragma unroll
        for (int mt = 0; mt < 2; mt++)
#pragma unroll
            for (int nt = 0; nt < 4; nt++)
#pragma unroll
                for (int j = 0; j < 4; j++) acc[mt][nt][j] = 0.f;

#pragma unroll
        for (int ks = 0; ks < 16; ks++) {
            int k0 = ks * 8;
            uint32_t af[2][4];
#pragma unroll
            for (int mt = 0; mt < 2; mt++) {
                int r = wr * 32 + mt * 16 + qid;
                const uint32_t* ap = &As[r * AS_STRIDE + k0 + qln];
                af[mt][0] = ap[0];
                af[mt][2] = ap[4];
                af[mt][1] = ap[8 * AS_STRIDE];
                af[mt][3] = ap[8 * AS_STRIDE + 4];
            }
#pragma unroll
            for (int nt = 0; nt < 4; nt++) {
                int n0 = wc * 32 + nt * 8;
                uint32_t b0 = Ws[(k0 + qln) * WS_STRIDE + n0 + qid];
                uint32_t b1 = Ws[(k0 + 4 + qln) * WS_STRIDE + n0 + qid];
#pragma unroll
                for (int mt = 0; mt < 2; mt++)
                    mma_tf32(acc[mt][nt][0], acc[mt][nt][1], acc[mt][nt][2], acc[mt][nt][3],
                             af[mt][0], af[mt][1], af[mt][2], af[mt][3], b0, b1);
            }
        }

        const float* bias = Bp[w];
        float* outp = Op[w];
#pragma unroll
        for (int nt = 0; nt < 4; nt++) {
            int col = wc * 32 + nt * 8 + qln * 2;
            float b0v = bias[col], b1v = bias[col + 1];
#pragma unroll
            for (int mt = 0; mt < 2; mt++) {
                int r = row0 + wr * 32 + mt * 16 + qid;
                if (r < M)
                    *(float2*)&outp[(size_t)r * DD + col] =
                        make_float2(acc[mt][nt][0] + b0v, acc[mt][nt][1] + b1v);
                if (r + 8 < M)
                    *(float2*)&outp[(size_t)(r + 8) * DD + col] =
                        make_float2(acc[mt][nt][2] + b0v, acc[mt][nt][3] + b1v);
            }
        }
    }
}

// ---------------- FUSED: edge GEMM + attention + L2 prefetch of gathers ----------------
__global__ void __launch_bounds__(256, 2)
fused_edge_kernel(const float* __restrict__ EA, const float* __restrict__ We,
                  const float* __restrict__ Q, const float* __restrict__ K,
                  const float* __restrict__ V, const void* __restrict__ eidx,
                  int E, float* __restrict__ denom, float* __restrict__ AGG) {
    extern __shared__ uint32_t sm[];
    uint32_t* Ws  = sm;                         // [128][WS_STRIDE]
    uint32_t* As  = sm + WS_ELEMS;              // [64][AS_STRIDE], reused as Ef
    int* ssrc = (int*)(sm + WS_ELEMS + AS_ELEMS);
    int* sdst = ssrc + 64;

    int tid = threadIdx.x;
    int wid = tid >> 5;
    int lane = tid & 31;
    int is64 = g_is64;

    // stage We once
#pragma unroll
    for (int it = 0; it < 16; it++) {
        int idx = it * 256 + tid;
        int k = idx >> 5, c4 = idx & 31;
        float4 v = ((const float4*)(We + (size_t)k * DD))[c4];
        uint4 t = make_uint4(f2tf32(v.x), f2tf32(v.y), f2tf32(v.z), f2tf32(v.w));
        *(uint4*)&Ws[k * WS_STRIDE + c4 * 4] = t;
    }

    int wr = wid & 1, wc = wid >> 1;
    int qid = lane >> 2, qln = lane & 3;

    int ntiles = (E + 63) >> 6;
    int t_end = blockIdx.x * TPC + TPC;
    if (t_end > ntiles) t_end = ntiles;

    for (int t = blockIdx.x * TPC; t < t_end; t++) {
        int e0 = t << 6;
        __syncthreads();   // previous iteration's attention reads of As done

        // stage edge_attr tile (tf32) + indices
#pragma unroll
        for (int it = 0; it < 8; it++) {
            int idx = it * 256 + tid;
            int r = idx >> 5, c4 = idx & 31;
            float4 v = make_float4(0.f, 0.f, 0.f, 0.f);
            if (e0 + r < E) v = ((const float4*)(EA + (size_t)(e0 + r) * DD))[c4];
            uint4 tt = make_uint4(f2tf32(v.x), f2tf32(v.y), f2tf32(v.z), f2tf32(v.w));
            *(uint4*)&As[r * AS_STRIDE + c4 * 4] = tt;
        }
        if (tid < 64) {
            long long ee = (long long)(e0 + tid);
            int ok = (e0 + tid) < E;
            ssrc[tid] = ok ? load_idx(eidx, ee, is64) : 0;
            sdst[tid] = ok ? load_idx(eidx, (long long)E + ee, is64) : 0;
        }
        __syncthreads();

        // ---- L2 prefetch of this tile's q/k/v gather rows (consumed after MMA).
        // lane = (edge-within-warp)*4 + line; covers all 4x128B lines of each
        // 512B node row for this warp's 8 edges. 3 instructions per warp.
        {
            int le   = wid * 8 + (lane >> 2);   // matches attention assignment
            int part = (lane & 3) * 32;         // 128B line offset in floats
            int psrc = ssrc[le], pdst = sdst[le];
            const float* qb = Q + (size_t)pdst * DD + part;
            const float* kb = K + (size_t)psrc * DD + part;
            const float* vb = V + (size_t)psrc * DD + part;
            asm volatile("prefetch.global.L2 [%0];" :: "l"(qb));
            asm volatile("prefetch.global.L2 [%0];" :: "l"(kb));
            asm volatile("prefetch.global.L2 [%0];" :: "l"(vb));
        }

        // MMA: Ef_tile[64,128] = A_tile @ We
        float acc[2][4][4];
#pragma unroll
        for (int mt = 0; mt < 2; mt++)
#pragma unroll
            for (int nt = 0; nt < 4; nt++)
#pragma unroll
                for (int j = 0; j < 4; j++) acc[mt][nt][j] = 0.f;

#pragma unroll
        for (int ks = 0; ks < 16; ks++) {
            int k0 = ks * 8;
            uint32_t af[2][4];
#pragma unroll
            for (int mt = 0; mt < 2; mt++) {
                int r = wr * 32 + mt * 16 + qid;
                const uint32_t* ap = &As[r * AS_STRIDE + k0 + qln];
                af[mt][0] = ap[0];
                af[mt][2] = ap[4];
                af[mt][1] = ap[8 * AS_STRIDE];
                af[mt][3] = ap[8 * AS_STRIDE + 4];
            }
#pragma unroll
            for (int nt = 0; nt < 4; nt++) {
                int n0 = wc * 32 + nt * 8;
                uint32_t b0 = Ws[(k0 + qln) * WS_STRIDE + n0 + qid];
                uint32_t b1 = Ws[(k0 + 4 + qln) * WS_STRIDE + n0 + qid];
#pragma unroll
                for (int mt = 0; mt < 2; mt++)
                    mma_tf32(acc[mt][nt][0], acc[mt][nt][1], acc[mt][nt][2], acc[mt][nt][3],
                             af[mt][0], af[mt][1], af[mt][2], af[mt][3], b0, b1);
            }
        }
        __syncthreads();   // everyone done reading As

        // Ef tile -> smem (f32, reuse As)
        float* Es = (float*)As;
#pragma unroll
        for (int nt = 0; nt < 4; nt++) {
            int col = wc * 32 + nt * 8 + qln * 2;
#pragma unroll
            for (int mt = 0; mt < 2; mt++) {
                int r = wr * 32 + mt * 16 + qid;
                *(float2*)&Es[r * AS_STRIDE + col] =
                    make_float2(acc[mt][nt][0], acc[mt][nt][1]);
                *(float2*)&Es[(r + 8) * AS_STRIDE + col] =
                    make_float2(acc[mt][nt][2], acc[mt][nt][3]);
            }
        }
        __syncthreads();

        // attention: warp wid handles edges e0 + wid*8 .. +7
#pragma unroll
        for (int i = 0; i < 8; i++) {
            int le = wid * 8 + i;
            bool ok = (e0 + le) < E;
            int src = ssrc[le], dst = sdst[le];

            float4 e4 = *(const float4*)&Es[le * AS_STRIDE + lane * 4];
            float4 q4 = *(const float4*)&Q[(size_t)dst * DD + lane * 4];
            float4 k4 = *(const float4*)&K[(size_t)src * DD + lane * 4];
            float4 v4 = *(const float4*)&V[(size_t)src * DD + lane * 4];

            float p = q4.x * (k4.x + e4.x) + q4.y * (k4.y + e4.y) +
                      q4.z * (k4.z + e4.z) + q4.w * (k4.w + e4.w);
            p += __shfl_xor_sync(0xffffffffu, p, 1);
            p += __shfl_xor_sync(0xffffffffu, p, 2);

            float ex = expf(p * 0.25f);
            if (ok) {
                if ((lane & 3) == 0)
                    atomicAdd(&denom[(size_t)dst * 8 + (lane >> 2)], ex);
                float m0 = ex * (v4.x + e4.x);
                float m1 = ex * (v4.y + e4.y);
                float m2 = ex * (v4.z + e4.z);
                float m3 = ex * (v4.w + e4.w);
                float* o = &AGG[(size_t)dst * DD + lane * 4];
                asm volatile("red.global.add.v4.f32 [%0], {%1,%2,%3,%4};"
                             :: "l"(o), "f"(m0), "f"(m1), "f"(m2), "f"(m3) : "memory");
            }
        }
    }
}

// ---------------- FUSED FFN: out = H + LN(silu(H@W1+b1)@W2 + b2) ----------------
__global__ void __launch_bounds__(256, 2)
ffn_kernel(const float* __restrict__ H,
           const float* __restrict__ W1, const float* __restrict__ b1,
           const float* __restrict__ W2, const float* __restrict__ b2,
           const float* __restrict__ g, const float* __restrict__ be,
           float* __restrict__ outp, int M) {
    extern __shared__ uint32_t sm[];
    uint32_t* As = sm;
    uint32_t* Ws = sm + AS_ELEMS;

    int tid = threadIdx.x;
    int wid = tid >> 5;
    int lane = tid & 31;
    int row0 = blockIdx.x * 64;

#pragma unroll
    for (int it = 0; it < 8; it++) {
        int idx = it * 256 + tid;
        int r = idx >> 5, c4 = idx & 31;
        float4 v = make_float4(0.f, 0.f, 0.f, 0.f);
        if (row0 + r < M) v = ((const float4*)(H + (size_t)(row0 + r) * DD))[c4];
        uint4 t = make_uint4(f2tf32(v.x), f2tf32(v.y), f2tf32(v.z), f2tf32(v.w));
        *(uint4*)&As[r * AS_STRIDE + c4 * 4] = t;
    }
#pragma unroll
    for (int it = 0; it < 16; it++) {
        int idx = it * 256 + tid;
        int k = idx >> 5, c4 = idx & 31;
        float4 v = ((const float4*)(W1 + (size_t)k * DD))[c4];
        uint4 t = make_uint4(f2tf32(v.x), f2tf32(v.y), f2tf32(v.z), f2tf32(v.w));
        *(uint4*)&Ws[k * WS_STRIDE + c4 * 4] = t;
    }
    __syncthreads();

    int wr = wid & 1, wc = wid >> 1;
    int qid = lane >> 2, qln = lane & 3;

    float acc[2][4][4];
#pragma unroll
    for (int mt = 0; mt < 2; mt++)
#pragma unroll
        for (int nt = 0; nt < 4; nt++)
#pragma unroll
            for (int j = 0; j < 4; j++) acc[mt][nt][j] = 0.f;

#pragma unroll
    for (int ks = 0; ks < 16; ks++) {
        int k0 = ks * 8;
        uint32_t af[2][4];
#pragma unroll
        for (int mt = 0; mt < 2; mt++) {
            int r = wr * 32 + mt * 16 + qid;
            const uint32_t* ap = &As[r * AS_STRIDE + k0 + qln];
            af[mt][0] = ap[0];
            af[mt][2] = ap[4];
            af[mt][1] = ap[8 * AS_STRIDE];
            af[mt][3] = ap[8 * AS_STRIDE + 4];
        }
#pragma unroll
        for (int nt = 0; nt < 4; nt++) {
            int n0 = wc * 32 + nt * 8;
            uint32_t b0 = Ws[(k0 + qln) * WS_STRIDE + n0 + qid];
            uint32_t b1v = Ws[(k0 + 4 + qln) * WS_STRIDE + n0 + qid];
#pragma unroll
            for (int mt = 0; mt < 2; mt++)
                mma_tf32(acc[mt][nt][0], acc[mt][nt][1], acc[mt][nt][2], acc[mt][nt][3],
                         af[mt][0], af[mt][1], af[mt][2], af[mt][3], b0, b1v);
        }
    }
    __syncthreads();

#pragma unroll
    for (int nt = 0; nt < 4; nt++) {
        int col = wc * 32 + nt * 8 + qln * 2;
        float c0 = b1[col], c1 = b1[col + 1];
#pragma unroll
        for (int mt = 0; mt < 2; mt++) {
            int r = wr * 32 + mt * 16 + qid;
            float o0 = acc[mt][nt][0] + c0;
            float o1 = acc[mt][nt][1] + c1;
            float o2 = acc[mt][nt][2] + c0;
            float o3 = acc[mt][nt][3] + c1;
            o0 = o0 / (1.f + expf(-o0));
            o1 = o1 / (1.f + expf(-o1));
            o2 = o2 / (1.f + expf(-o2));
            o3 = o3 / (1.f + expf(-o3));
            As[r * AS_STRIDE + col]           = f2tf32(o0);
            As[r * AS_STRIDE + col + 1]       = f2tf32(o1);
            As[(r + 8) * AS_STRIDE + col]     = f2tf32(o2);
            As[(r + 8) * AS_STRIDE + col + 1] = f2tf32(o3);
        }
    }
#pragma unroll
    for (int it = 0; it < 16; it++) {
        int idx = it * 256 + tid;
        int k = idx >> 5, c4 = idx & 31;
        float4 v = ((const float4*)(W2 + (size_t)k * DD))[c4];
        uint4 t = make_uint4(f2tf32(v.x), f2tf32(v.y), f2tf32(v.z), f2tf32(v.w));
        *(uint4*)&Ws[k * WS_STRIDE + c4 * 4] = t;
    }
    __syncthreads();

#pragma unroll
    for (int mt = 0; mt < 2; mt++)
#pragma unroll
        for (int nt = 0; nt < 4; nt++)
#pragma unroll
            for (int j = 0; j < 4; j++) acc[mt][nt][j] = 0.f;

#pragma unroll
    for (int ks = 0; ks < 16; ks++) {
        int k0 = ks * 8;
        uint32_t af[2][4];
#pragma unroll
        for (int mt = 0; mt < 2; mt++) {
            int r = wr * 32 + mt * 16 + qid;
            const uint32_t* ap = &As[r * AS_STRIDE + k0 + qln];
            af[mt][0] = ap[0];
            af[mt][2] = ap[4];
            af[mt][1] = ap[8 * AS_STRIDE];
            af[mt][3] = ap[8 * AS_STRIDE + 4];
        }
#pragma unroll
        for (int nt = 0; nt < 4; nt++) {
            int n0 = wc * 32 + nt * 8;
            uint32_t b0 = Ws[(k0 + qln) * WS_STRIDE + n0 + qid];
            uint32_t b1v = Ws[(k0 + 4 + qln) * WS_STRIDE + n0 + qid];
#pragma unroll
            for (int mt = 0; mt < 2; mt++)
                mma_tf32(acc[mt][nt][0], acc[mt][nt][1], acc[mt][nt][2], acc[mt][nt][3],
                         af[mt][0], af[mt][1], af[mt][2], af[mt][3], b0, b1v);
        }
    }
    __syncthreads();

    float* Es = (float*)Ws;
#pragma unroll
    for (int nt = 0; nt < 4; nt++) {
        int col = wc * 32 + nt * 8 + qln * 2;
        float c0 = b2[col], c1 = b2[col + 1];
#pragma unroll
        for (int mt = 0; mt < 2; mt++) {
            int r = wr * 32 + mt * 16 + qid;
            *(float2*)&Es[r * AS_STRIDE + col] =
                make_float2(acc[mt][nt][0] + c0, acc[mt][nt][1] + c1);
            *(float2*)&Es[(r + 8) * AS_STRIDE + col] =
                make_float2(acc[mt][nt][2] + c0, acc[mt][nt][3] + c1);
        }
    }
    __syncthreads();

#pragma unroll
    for (int i = 0; i < 8; i++) {
        int r = wid * 8 + i;
        float4 o = *(float4*)&Es[r * AS_STRIDE + lane * 4];

        float sum = o.x + o.y + o.z + o.w;
#pragma unroll
        for (int off = 16; off >= 1; off >>= 1)
            sum += __shfl_xor_sync(0xffffffffu, sum, off);
        float mu = sum * (1.0f / 128.0f);

        float dx = o.x - mu, dy = o.y - mu, dz = o.z - mu, dw = o.w - mu;
        float ss = dx * dx + dy * dy + dz * dz + dw * dw;
#pragma unroll
        for (int off = 16; off >= 1; off >>= 1)
            ss += __shfl_xor_sync(0xffffffffu, ss, off);
        float rs = rsqrtf(ss * (1.0f / 128.0f) + 1e-5f);

        if (row0 + r < M) {
            float4 gg = *(const float4*)&g[lane * 4];
            float4 bb = *(const float4*)&be[lane * 4];
            float4 hh = *(const float4*)&H[(size_t)(row0 + r) * DD + lane * 4];
            float4 rr;
            rr.x = hh.x + dx * rs * gg.x + bb.x;
            rr.y = hh.y + dy * rs * gg.y + bb.y;
            rr.z = hh.z + dz * rs * gg.z + bb.z;
            rr.w = hh.w + dw * rs * gg.w + bb.w;
            *(float4*)&outp[(size_t)(row0 + r) * DD + lane * 4] = rr;
        }
    }
}

// ---------------- edge index dtype detection ----------------
__global__ void detect_idx_kernel(const long long* __restrict__ p, int E, int N) {
    if (threadIdx.x == 0 && blockIdx.x == 0) {
        int ok64 = 1;
        int n = (E < 64) ? E : 64;
        for (int i = 0; i < n; i++) {
            long long v = p[i];
            if (v < 0 || v >= (long long)N) { ok64 = 0; break; }
        }
        g_is64 = ok64;
    }
}

// ---------------- zero accumulators ----------------
__global__ void zero_kernel(float* __restrict__ a, size_t na,
                            float* __restrict__ b, size_t nb) {
    size_t i = (size_t)blockIdx.x * blockDim.x + threadIdx.x;
    size_t stride = (size_t)gridDim.x * blockDim.x;
    for (size_t j = i; j < na; j += stride) a[j] = 0.0f;
    for (size_t j = i; j < nb; j += stride) b[j] = 0.0f;
}

// ---------------- h = x + LN(AGG/den + SKIP) ----------------
__global__ void postln1_kernel(const float* __restrict__ x, const float* __restrict__ AGG,
                               const float* __restrict__ SKIP, const float* __restrict__ den,
                               const float* __restrict__ g, const float* __restrict__ b,
                               float* __restrict__ outp, int M) {
    long long gw = ((long long)blockIdx.x * blockDim.x + threadIdx.x) >> 5;
    int lane = threadIdx.x & 31;
    if (gw >= M) return;

    float dh = den[(size_t)gw * 8 + (lane >> 2)];
    float inv = 1.0f / (dh + 1e-16f);

    float4 o = *(const float4*)&AGG[(size_t)gw * DD + lane * 4];
    float4 s = *(const float4*)&SKIP[(size_t)gw * DD + lane * 4];
    o.x = o.x * inv + s.x;
    o.y = o.y * inv + s.y;
    o.z = o.z * inv + s.z;
    o.w = o.w * inv + s.w;

    float sum = o.x + o.y + o.z + o.w;
#pragma unroll
    for (int off = 16; off >= 1; off >>= 1) sum += __shfl_xor_sync(0xffffffffu, sum, off);
    float mu = sum * (1.0f / 128.0f);

    float dx = o.x - mu, dy = o.y - mu, dz = o.z - mu, dw = o.w - mu;
    float ss = dx * dx + dy * dy + dz * dz + dw * dw;
#pragma unroll
    for (int off = 16; off >= 1; off >>= 1) ss += __shfl_xor_sync(0xffffffffu, ss, off);
    float rs = rsqrtf(ss * (1.0f / 128.0f) + 1e-5f);

    float4 gg = *(const float4*)&g[lane * 4];
    float4 bb = *(const float4*)&b[lane * 4];
    float4 xx = *(const float4*)&x[(size_t)gw * DD + lane * 4];

    float4 r;
    r.x = xx.x + dx * rs * gg.x + bb.x;
    r.y = xx.y + dy * rs * gg.y + bb.y;
    r.z = xx.z + dz * rs * gg.z + bb.z;
    r.w = xx.w + dw * rs * gg.w + bb.w;
    *(float4*)&outp[(size_t)gw * DD + lane * 4] = r;
}

// ---------------- launch ----------------
extern "C" void kernel_launch(void* const* d_in, const int* in_sizes, int n_in,
                              void* d_out, int out_size) {
    const void*  eidx      = d_in[0];
    const float* x         = (const float*)d_in[1];
    const float* edge_attr = (const float*)d_in[2];
    const float* Wq = (const float*)d_in[3],  *bq = (const float*)d_in[4];
    const float* Wk = (const float*)d_in[5],  *bk = (const float*)d_in[6];
    const float* Wv = (const float*)d_in[7],  *bv = (const float*)d_in[8];
    const float* We = (const float*)d_in[9];
    const float* Wskip = (const float*)d_in[10], *bskip = (const float*)d_in[11];
    const float* W1 = (const float*)d_in[12], *b1 = (const float*)d_in[13];
    const float* W2 = (const float*)d_in[14], *b2 = (const float*)d_in[15];
    const float* g1 = (const float*)d_in[16], *be1 = (const float*)d_in[17];
    const float* g2 = (const float*)d_in[18], *be2 = (const float*)d_in[19];
    float* out = (float*)d_out;

    int N = in_sizes[1] / DD;   // 100000
    int E = in_sizes[2] / DD;   // 600000

    float *pQ, *pK, *pV, *pSK, *pAGG, *pH, *pDen;
    cudaGetSymbolAddress((void**)&pQ,   g_Q);
    cudaGetSymbolAddress((void**)&pK,   g_K);
    cudaGetSymbolAddress((void**)&pV,   g_V);
    cudaGetSymbolAddress((void**)&pSK,  g_SKIP);
    cudaGetSymbolAddress((void**)&pAGG, g_AGG);
    cudaGetSymbolAddress((void**)&pH,   g_H);
    cudaGetSymbolAddress((void**)&pDen, g_den);

    cudaFuncSetAttribute(mma_gemm_kernel, cudaFuncAttributeMaxDynamicSharedMemorySize,
                         GEMM_SMEM);
    cudaFuncSetAttribute(fused_edge_kernel, cudaFuncAttributeMaxDynamicSharedMemorySize,
                         FUSED_SMEM);
    cudaFuncSetAttribute(ffn_kernel, cudaFuncAttributeMaxDynamicSharedMemorySize,
                         FFN_SMEM);

    detect_idx_kernel<<<1, 32>>>((const long long*)eidx, E, N);
    zero_kernel<<<1024, 256>>>(pDen, (size_t)N * 8, pAGG, (size_t)N * DD);

    // node projections
    int nb_node = (N + 63) / 64;
    mma_gemm_kernel<<<nb_node, 256, GEMM_SMEM>>>(x, N, 4,
        Wq, Wk, Wv, Wskip, bq, bk, bv, bskip, pQ, pK, pV, pSK);

    // fused edge GEMM + attention (with gather prefetch)
    int ntiles = (E + 63) / 64;
    int nb_fused = (ntiles + TPC - 1) / TPC;
    fused_edge_kernel<<<nb_fused, 256, FUSED_SMEM>>>(edge_attr, We, pQ, pK, pV,
                                                     eidx, E, pDen, pAGG);

    // h = x + LN(AGG/den + skip)
    int nbw = (N + 7) / 8;
    postln1_kernel<<<nbw, 256>>>(x, pAGG, pSK, pDen, g1, be1, pH, N);

    // fused FFN + final LN + residual -> out
    ffn_kernel<<<nb_node, 256, FFN_SMEM>>>(pH, W1, b1, W2, b2, g2, be2, out, N);
}

// round 10
// speedup vs baseline: 1.3094x; 1.0613x over previous
#include <cuda_runtime.h>
#include <cstdint>
#include <cstddef>

// Problem constants
#define NN 100000
#define EE 600000
#define DD 128

// ---------------- scratch ----------------
__device__ float g_Q   [(size_t)NN * DD];
__device__ float g_K   [(size_t)NN * DD];
__device__ float g_V   [(size_t)NN * DD];
__device__ float g_SKIP[(size_t)NN * DD];
__device__ float g_AGG [(size_t)NN * DD];
__device__ float g_H   [(size_t)NN * DD];
__device__ float g_den [(size_t)NN * 8];
__device__ int   g_is64;

// ---------------- tf32 helpers ----------------
__device__ __forceinline__ uint32_t f2tf32(float v) {
    uint32_t r;
    asm("cvt.rna.tf32.f32 %0, %1;" : "=r"(r) : "f"(v));
    return r;
}
__device__ __forceinline__ void mma_tf32(float& d0, float& d1, float& d2, float& d3,
                                         uint32_t a0, uint32_t a1, uint32_t a2, uint32_t a3,
                                         uint32_t b0, uint32_t b1) {
    asm volatile(
        "mma.sync.aligned.m16n8k8.row.col.f32.tf32.tf32.f32 "
        "{%0,%1,%2,%3}, {%4,%5,%6,%7}, {%8,%9}, {%0,%1,%2,%3};"
        : "+f"(d0), "+f"(d1), "+f"(d2), "+f"(d3)
        : "r"(a0), "r"(a1), "r"(a2), "r"(a3), "r"(b0), "r"(b1));
}

#define AS_STRIDE 132
#define WS_STRIDE 136
#define AS_ELEMS  (64 * AS_STRIDE)                 // 8448
#define WS_ELEMS  (128 * WS_STRIDE)                // 17408
#define GEMM_SMEM ((AS_ELEMS + WS_ELEMS) * 4)      // 103424 -> 2 CTAs/SM
#define FFN_SMEM  GEMM_SMEM
#define FUSED_SMEM (GEMM_SMEM + 64 * 2 * 4)

#define TPC 8   // 64-edge tiles per CTA in fused edge kernel

__device__ __forceinline__ int load_idx(const void* p, long long i, int is64) {
    if (is64) return (int)((const long long*)p)[i];
    return ((const int*)p)[i];
}

// ---------------- node projection GEMM (Q,K,V,SKIP share staged x) ----------------
__global__ void __launch_bounds__(256, 2)
mma_gemm_kernel(const float* __restrict__ A, int M, int nw,
                const float* Wg0, const float* Wg1, const float* Wg2, const float* Wg3,
                const float* bg0, const float* bg1, const float* bg2, const float* bg3,
                float* og0, float* og1, float* og2, float* og3) {
    extern __shared__ uint32_t sm[];
    uint32_t* As = sm;
    uint32_t* Ws = sm + AS_ELEMS;

    int tid = threadIdx.x;
    int wid = tid >> 5;
    int lane = tid & 31;
    int row0 = blockIdx.x * 64;

    const float* Wp[4] = {Wg0, Wg1, Wg2, Wg3};
    const float* Bp[4] = {bg0, bg1, bg2, bg3};
    float*       Op[4] = {og0, og1, og2, og3};

#pragma unroll
    for (int it = 0; it < 8; it++) {
        int idx = it * 256 + tid;
        int r = idx >> 5, c4 = idx & 31;
        float4 v = make_float4(0.f, 0.f, 0.f, 0.f);
        if (row0 + r < M) v = ((const float4*)(A + (size_t)(row0 + r) * DD))[c4];
        uint4 t = make_uint4(f2tf32(v.x), f2tf32(v.y), f2tf32(v.z), f2tf32(v.w));
        *(uint4*)&As[r * AS_STRIDE + c4 * 4] = t;
    }

    int wr = wid & 1, wc = wid >> 1;
    int qid = lane >> 2, qln = lane & 3;

    for (int w = 0; w < nw; w++) {
        __syncthreads();
        const float* Wgp = Wp[w];
#pragma unroll
        for (int it = 0; it < 16; it++) {
            int idx = it * 256 + tid;
            int k = idx >> 5, c4 = idx & 31;
            float4 v = ((const float4*)(Wgp + (size_t)k * DD))[c4];
            uint4 t = make_uint4(f2tf32(v.x), f2tf32(v.y), f2tf32(v.z), f2tf32(v.w));
            *(uint4*)&Ws[k * WS_STRIDE + c4 * 4] = t;
        }
        __syncthreads();

        float acc[2][4][4];
#pragma unroll
        for (int mt = 0; mt < 2; mt++)
#pragma unroll
            for (int nt = 0; nt < 4; nt++)
#pragma unroll
                for (int j = 0; j < 4; j++) acc[mt][nt][j] = 0.f;

#pragma unroll
        for (int ks = 0; ks < 16; ks++) {
            int k0 = ks * 8;
            uint32_t af[2][4];
#pragma unroll
            for (int mt = 0; mt < 2; mt++) {
                int r = wr * 32 + mt * 16 + qid;
                const uint32_t* ap = &As[r * AS_STRIDE + k0 + qln];
                af[mt][0] = ap[0];
                af[mt][2] = ap[4];
                af[mt][1] = ap[8 * AS_STRIDE];
                af[mt][3] = ap[8 * AS_STRIDE + 4];
            }
#pragma unroll
            for (int nt = 0; nt < 4; nt++) {
                int n0 = wc * 32 + nt * 8;
                uint32_t b0 = Ws[(k0 + qln) * WS_STRIDE + n0 + qid];
                uint32_t b1 = Ws[(k0 + 4 + qln) * WS_STRIDE + n0 + qid];
#pragma unroll
                for (int mt = 0; mt < 2; mt++)
                    mma_tf32(acc[mt][nt][0], acc[mt][nt][1], acc[mt][nt][2], acc[mt][nt][3],
                             af[mt][0], af[mt][1], af[mt][2], af[mt][3], b0, b1);
            }
        }

        const float* bias = Bp[w];
        float* outp = Op[w];
#pragma unroll
        for (int nt = 0; nt < 4; nt++) {
            int col = wc * 32 + nt * 8 + qln * 2;
            float b0v = bias[col], b1v = bias[col + 1];
#pragma unroll
            for (int mt = 0; mt < 2; mt++) {
                int r = row0 + wr * 32 + mt * 16 + qid;
                if (r < M)
                    *(float2*)&outp[(size_t)r * DD + col] =
                        make_float2(acc[mt][nt][0] + b0v, acc[mt][nt][1] + b1v);
                if (r + 8 < M)
                    *(float2*)&outp[(size_t)(r + 8) * DD + col] =
                        make_float2(acc[mt][nt][2] + b0v, acc[mt][nt][3] + b1v);
            }
        }
    }
}

// ---------------- FUSED: edge GEMM + attention, 512 threads (16 warps) ----------------
// Same 64-edge tile + smem as R9, but 2x warps per CTA -> 32 warps/SM.
// MMA: 4 row-groups x 4 col-groups, each warp 16 rows x 32 cols.
// Attention: 4 edges/warp, low-ILP (latency hidden by warp count).
__global__ void __launch_bounds__(512, 2)
fused_edge_kernel(const float* __restrict__ EA, const float* __restrict__ We,
                  const float* __restrict__ Q, const float* __restrict__ K,
                  const float* __restrict__ V, const void* __restrict__ eidx,
                  int E, float* __restrict__ denom, float* __restrict__ AGG) {
    extern __shared__ uint32_t sm[];
    uint32_t* Ws  = sm;                         // [128][WS_STRIDE]
    uint32_t* As  = sm + WS_ELEMS;              // [64][AS_STRIDE], reused as Ef
    int* ssrc = (int*)(sm + WS_ELEMS + AS_ELEMS);
    int* sdst = ssrc + 64;

    int tid = threadIdx.x;
    int wid = tid >> 5;
    int lane = tid & 31;
    int is64 = g_is64;

    // stage We once (4096 float4 / 512 threads = 8 iters)
#pragma unroll
    for (int it = 0; it < 8; it++) {
        int idx = it * 512 + tid;
        int k = idx >> 5, c4 = idx & 31;
        float4 v = ((const float4*)(We + (size_t)k * DD))[c4];
        uint4 t = make_uint4(f2tf32(v.x), f2tf32(v.y), f2tf32(v.z), f2tf32(v.w));
        *(uint4*)&Ws[k * WS_STRIDE + c4 * 4] = t;
    }

    int wr = wid & 3;        // row group: rows wr*16 .. +15
    int wc = wid >> 2;       // col group: cols wc*32 .. +31
    int qid = lane >> 2, qln = lane & 3;

    int ntiles = (E + 63) >> 6;
    int t_end = blockIdx.x * TPC + TPC;
    if (t_end > ntiles) t_end = ntiles;

    for (int t = blockIdx.x * TPC; t < t_end; t++) {
        int e0 = t << 6;
        __syncthreads();   // previous iteration's attention reads of As done

        // stage edge_attr tile (tf32): 2048 float4 / 512 = 4 iters
#pragma unroll
        for (int it = 0; it < 4; it++) {
            int idx = it * 512 + tid;
            int r = idx >> 5, c4 = idx & 31;
            float4 v = make_float4(0.f, 0.f, 0.f, 0.f);
            if (e0 + r < E) v = ((const float4*)(EA + (size_t)(e0 + r) * DD))[c4];
            uint4 tt = make_uint4(f2tf32(v.x), f2tf32(v.y), f2tf32(v.z), f2tf32(v.w));
            *(uint4*)&As[r * AS_STRIDE + c4 * 4] = tt;
        }
        if (tid < 64) {
            long long ee = (long long)(e0 + tid);
            int ok = (e0 + tid) < E;
            ssrc[tid] = ok ? load_idx(eidx, ee, is64) : 0;
            sdst[tid] = ok ? load_idx(eidx, (long long)E + ee, is64) : 0;
        }
        __syncthreads();

        // L2 prefetch of this tile's q/k/v gather rows (consumed after MMA).
        // Each warp covers its 4 attention edges; lanes 0-15 hit the 4x128B
        // lines (lanes 16-31 duplicate — merged in the LSU queue).
        {
            int le   = wid * 4 + (lane >> 3);
            int part = (lane & 3) * 32;
            int psrc = ssrc[le], pdst = sdst[le];
            const float* qb = Q + (size_t)pdst * DD + part;
            const float* kb = K + (size_t)psrc * DD + part;
            const float* vb = V + (size_t)psrc * DD + part;
            asm volatile("prefetch.global.L2 [%0];" :: "l"(qb));
            asm volatile("prefetch.global.L2 [%0];" :: "l"(kb));
            asm volatile("prefetch.global.L2 [%0];" :: "l"(vb));
        }

        // MMA: Ef_tile[64,128] = A_tile @ We; this warp: rows wr*16..+15,
        // cols wc*32..+31 (1 m-tile x 4 n-tiles of m16n8k8)
        float acc[4][4];
#pragma unroll
        for (int nt = 0; nt < 4; nt++)
#pragma unroll
            for (int j = 0; j < 4; j++) acc[nt][j] = 0.f;

#pragma unroll
        for (int ks = 0; ks < 16; ks++) {
            int k0 = ks * 8;
            const uint32_t* ap = &As[(wr * 16 + qid) * AS_STRIDE + k0 + qln];
            uint32_t a0 = ap[0];
            uint32_t a2 = ap[4];
            uint32_t a1 = ap[8 * AS_STRIDE];
            uint32_t a3 = ap[8 * AS_STRIDE + 4];
#pragma unroll
            for (int nt = 0; nt < 4; nt++) {
                int n0 = wc * 32 + nt * 8;
                uint32_t b0 = Ws[(k0 + qln) * WS_STRIDE + n0 + qid];
                uint32_t b1 = Ws[(k0 + 4 + qln) * WS_STRIDE + n0 + qid];
                mma_tf32(acc[nt][0], acc[nt][1], acc[nt][2], acc[nt][3],
                         a0, a1, a2, a3, b0, b1);
            }
        }
        __syncthreads();   // everyone done reading As

        // Ef tile -> smem (f32, reuse As)
        float* Es = (float*)As;
#pragma unroll
        for (int nt = 0; nt < 4; nt++) {
            int col = wc * 32 + nt * 8 + qln * 2;
            int r = wr * 16 + qid;
            *(float2*)&Es[r * AS_STRIDE + col] =
                make_float2(acc[nt][0], acc[nt][1]);
            *(float2*)&Es[(r + 8) * AS_STRIDE + col] =
                make_float2(acc[nt][2], acc[nt][3]);
        }
        __syncthreads();

        // attention: warp wid handles edges e0 + wid*4 .. +3 (low ILP on purpose)
        for (int i = 0; i < 4; i++) {
            int le = wid * 4 + i;
            bool ok = (e0 + le) < E;
            int src = ssrc[le], dst = sdst[le];

            float4 e4 = *(const float4*)&Es[le * AS_STRIDE + lane * 4];
            float4 q4 = *(const float4*)&Q[(size_t)dst * DD + lane * 4];
            float4 k4 = *(const float4*)&K[(size_t)src * DD + lane * 4];

            float p = q4.x * (k4.x + e4.x) + q4.y * (k4.y + e4.y) +
                      q4.z * (k4.z + e4.z) + q4.w * (k4.w + e4.w);
            p += __shfl_xor_sync(0xffffffffu, p, 1);
            p += __shfl_xor_sync(0xffffffffu, p, 2);

            float ex = expf(p * 0.25f);
            float4 v4 = *(const float4*)&V[(size_t)src * DD + lane * 4];
            if (ok) {
                if ((lane & 3) == 0)
                    atomicAdd(&denom[(size_t)dst * 8 + (lane >> 2)], ex);
                float m0 = ex * (v4.x + e4.x);
                float m1 = ex * (v4.y + e4.y);
                float m2 = ex * (v4.z + e4.z);
                float m3 = ex * (v4.w + e4.w);
                float* o = &AGG[(size_t)dst * DD + lane * 4];
                asm volatile("red.global.add.v4.f32 [%0], {%1,%2,%3,%4};"
                             :: "l"(o), "f"(m0), "f"(m1), "f"(m2), "f"(m3) : "memory");
            }
        }
    }
}

// ---------------- FUSED FFN: out = H + LN(silu(H@W1+b1)@W2 + b2) ----------------
__global__ void __launch_bounds__(256, 2)
ffn_kernel(const float* __restrict__ H,
           const float* __restrict__ W1, const float* __restrict__ b1,
           const float* __restrict__ W2, const float* __restrict__ b2,
           const float* __restrict__ g, const float* __restrict__ be,
           float* __restrict__ outp, int M) {
    extern __shared__ uint32_t sm[];
    uint32_t* As = sm;
    uint32_t* Ws = sm + AS_ELEMS;

    int tid = threadIdx.x;
    int wid = tid >> 5;
    int lane = tid & 31;
    int row0 = blockIdx.x * 64;

#pragma unroll
    for (int it = 0; it < 8; it++) {
        int idx = it * 256 + tid;
        int r = idx >> 5, c4 = idx & 31;
        float4 v = make_float4(0.f, 0.f, 0.f, 0.f);
        if (row0 + r < M) v = ((const float4*)(H + (size_t)(row0 + r) * DD))[c4];
        uint4 t = make_uint4(f2tf32(v.x), f2tf32(v.y), f2tf32(v.z), f2tf32(v.w));
        *(uint4*)&As[r * AS_STRIDE + c4 * 4] = t;
    }
#pragma unroll
    for (int it = 0; it < 16; it++) {
        int idx = it * 256 + tid;
        int k = idx >> 5, c4 = idx & 31;
        float4 v = ((const float4*)(W1 + (size_t)k * DD))[c4];
        uint4 t = make_uint4(f2tf32(v.x), f2tf32(v.y), f2tf32(v.z), f2tf32(v.w));
        *(uint4*)&Ws[k * WS_STRIDE + c4 * 4] = t;
    }
    __syncthreads();

    int wr = wid & 1, wc = wid >> 1;
    int qid = lane >> 2, qln = lane & 3;

    float acc[2][4][4];
#pragma unroll
    for (int mt = 0; mt < 2; mt++)
#pragma unroll
        for (int nt = 0; nt < 4; nt++)
#pragma unroll
            for (int j = 0; j < 4; j++) acc[mt][nt][j] = 0.f;

#pragma unroll
    for (int ks = 0; ks < 16; ks++) {
        int k0 = ks * 8;
        uint32_t af[2][4];
#pragma unroll
        for (int mt = 0; mt < 2; mt++) {
            int r = wr * 32 + mt * 16 + qid;
            const uint32_t* ap = &As[r * AS_STRIDE + k0 + qln];
            af[mt][0] = ap[0];
            af[mt][2] = ap[4];
            af[mt][1] = ap[8 * AS_STRIDE];
            af[mt][3] = ap[8 * AS_STRIDE + 4];
        }
#pragma unroll
        for (int nt = 0; nt < 4; nt++) {
            int n0 = wc * 32 + nt * 8;
            uint32_t b0 = Ws[(k0 + qln) * WS_STRIDE + n0 + qid];
            uint32_t b1v = Ws[(k0 + 4 + qln) * WS_STRIDE + n0 + qid];
#pragma unroll
            for (int mt = 0; mt < 2; mt++)
                mma_tf32(acc[mt][nt][0], acc[mt][nt][1], acc[mt][nt][2], acc[mt][nt][3],
                         af[mt][0], af[mt][1], af[mt][2], af[mt][3], b0, b1v);
        }
    }
    __syncthreads();

#pragma unroll
    for (int nt = 0; nt < 4; nt++) {
        int col = wc * 32 + nt * 8 + qln * 2;
        float c0 = b1[col], c1 = b1[col + 1];
#pragma unroll
        for (int mt = 0; mt < 2; mt++) {
            int r = wr * 32 + mt * 16 + qid;
            float o0 = acc[mt][nt][0] + c0;
            float o1 = acc[mt][nt][1] + c1;
            float o2 = acc[mt][nt][2] + c0;
            float o3 = acc[mt][nt][3] + c1;
            o0 = o0 / (1.f + expf(-o0));
            o1 = o1 / (1.f + expf(-o1));
            o2 = o2 / (1.f + expf(-o2));
            o3 = o3 / (1.f + expf(-o3));
            As[r * AS_STRIDE + col]           = f2tf32(o0);
            As[r * AS_STRIDE + col + 1]       = f2tf32(o1);
            As[(r + 8) * AS_STRIDE + col]     = f2tf32(o2);
            As[(r + 8) * AS_STRIDE + col + 1] = f2tf32(o3);
        }
    }
#pragma unroll
    for (int it = 0; it < 16; it++) {
        int idx = it * 256 + tid;
        int k = idx >> 5, c4 = idx & 31;
        float4 v = ((const float4*)(W2 + (size_t)k * DD))[c4];
        uint4 t = make_uint4(f2tf32(v.x), f2tf32(v.y), f2tf32(v.z), f2tf32(v.w));
        *(uint4*)&Ws[k * WS_STRIDE + c4 * 4] = t;
    }
    __syncthreads();

#pragma unroll
    for (int mt = 0; mt < 2; mt++)
#pragma unroll
        for (int nt = 0; nt < 4; nt++)
#pragma unroll
            for (int j = 0; j < 4; j++) acc[mt][nt][j] = 0.f;

#pragma unroll
    for (int ks = 0; ks < 16; ks++) {
        int k0 = ks * 8;
        uint32_t af[2][4];
#pragma unroll
        for (int mt = 0; mt < 2; mt++) {
            int r = wr * 32 + mt * 16 + qid;
            const uint32_t* ap = &As[r * AS_STRIDE + k0 + qln];
            af[mt][0] = ap[0];
            af[mt][2] = ap[4];
            af[mt][1] = ap[8 * AS_STRIDE];
            af[mt][3] = ap[8 * AS_STRIDE + 4];
        }
#pragma unroll
        for (int nt = 0; nt < 4; nt++) {
            int n0 = wc * 32 + nt * 8;
            uint32_t b0 = Ws[(k0 + qln) * WS_STRIDE + n0 + qid];
            uint32_t b1v = Ws[(k0 + 4 + qln) * WS_STRIDE + n0 + qid];
#pragma unroll
            for (int mt = 0; mt < 2; mt++)
                mma_tf32(acc[mt][nt][0], acc[mt][nt][1], acc[mt][nt][2], acc[mt][nt][3],
                         af[mt][0], af[mt][1], af[mt][2], af[mt][3], b0, b1v);
        }
    }
    __syncthreads();

    float* Es = (float*)Ws;
#pragma unroll
    for (int nt = 0; nt < 4; nt++) {
        int col = wc * 32 + nt * 8 + qln * 2;
        float c0 = b2[col], c1 = b2[col + 1];
#pragma unroll
        for (int mt = 0; mt < 2; mt++) {
            int r = wr * 32 + mt * 16 + qid;
            *(float2*)&Es[r * AS_STRIDE + col] =
                make_float2(acc[mt][nt][0] + c0, acc[mt][nt][1] + c1);
            *(float2*)&Es[(r + 8) * AS_STRIDE + col] =
                make_float2(acc[mt][nt][2] + c0, acc[mt][nt][3] + c1);
        }
    }
    __syncthreads();

#pragma unroll
    for (int i = 0; i < 8; i++) {
        int r = wid * 8 + i;
        float4 o = *(float4*)&Es[r * AS_STRIDE + lane * 4];

        float sum = o.x + o.y + o.z + o.w;
#pragma unroll
        for (int off = 16; off >= 1; off >>= 1)
            sum += __shfl_xor_sync(0xffffffffu, sum, off);
        float mu = sum * (1.0f / 128.0f);

        float dx = o.x - mu, dy = o.y - mu, dz = o.z - mu, dw = o.w - mu;
        float ss = dx * dx + dy * dy + dz * dz + dw * dw;
#pragma unroll
        for (int off = 16; off >= 1; off >>= 1)
            ss += __shfl_xor_sync(0xffffffffu, ss, off);
        float rs = rsqrtf(ss * (1.0f / 128.0f) + 1e-5f);

        if (row0 + r < M) {
            float4 gg = *(const float4*)&g[lane * 4];
            float4 bb = *(const float4*)&be[lane * 4];
            float4 hh = *(const float4*)&H[(size_t)(row0 + r) * DD + lane * 4];
            float4 rr;
            rr.x = hh.x + dx * rs * gg.x + bb.x;
            rr.y = hh.y + dy * rs * gg.y + bb.y;
            rr.z = hh.z + dz * rs * gg.z + bb.z;
            rr.w = hh.w + dw * rs * gg.w + bb.w;
            *(float4*)&outp[(size_t)(row0 + r) * DD + lane * 4] = rr;
        }
    }
}

// ---------------- edge index dtype detection ----------------
__global__ void detect_idx_kernel(const long long* __restrict__ p, int E, int N) {
    if (threadIdx.x == 0 && blockIdx.x == 0) {
        int ok64 = 1;
        int n = (E < 64) ? E : 64;
        for (int i = 0; i < n; i++) {
            long long v = p[i];
            if (v < 0 || v >= (long long)N) { ok64 = 0; break; }
        }
        g_is64 = ok64;
    }
}

// ---------------- zero accumulators ----------------
__global__ void zero_kernel(float* __restrict__ a, size_t na,
                            float* __restrict__ b, size_t nb) {
    size_t i = (size_t)blockIdx.x * blockDim.x + threadIdx.x;
    size_t stride = (size_t)gridDim.x * blockDim.x;
    for (size_t j = i; j < na; j += stride) a[j] = 0.0f;
    for (size_t j = i; j < nb; j += stride) b[j] = 0.0f;
}

// ---------------- h = x + LN(AGG/den + SKIP) ----------------
__global__ void postln1_kernel(const float* __restrict__ x, const float* __restrict__ AGG,
                               const float* __restrict__ SKIP, const float* __restrict__ den,
                               const float* __restrict__ g, const float* __restrict__ b,
                               float* __restrict__ outp, int M) {
    long long gw = ((long long)blockIdx.x * blockDim.x + threadIdx.x) >> 5;
    int lane = threadIdx.x & 31;
    if (gw >= M) return;

    float dh = den[(size_t)gw * 8 + (lane >> 2)];
    float inv = 1.0f / (dh + 1e-16f);

    float4 o = *(const float4*)&AGG[(size_t)gw * DD + lane * 4];
    float4 s = *(const float4*)&SKIP[(size_t)gw * DD + lane * 4];
    o.x = o.x * inv + s.x;
    o.y = o.y * inv + s.y;
    o.z = o.z * inv + s.z;
    o.w = o.w * inv + s.w;

    float sum = o.x + o.y + o.z + o.w;
#pragma unroll
    for (int off = 16; off >= 1; off >>= 1) sum += __shfl_xor_sync(0xffffffffu, sum, off);
    float mu = sum * (1.0f / 128.0f);

    float dx = o.x - mu, dy = o.y - mu, dz = o.z - mu, dw = o.w - mu;
    float ss = dx * dx + dy * dy + dz * dz + dw * dw;
#pragma unroll
    for (int off = 16; off >= 1; off >>= 1) ss += __shfl_xor_sync(0xffffffffu, ss, off);
    float rs = rsqrtf(ss * (1.0f / 128.0f) + 1e-5f);

    float4 gg = *(const float4*)&g[lane * 4];
    float4 bb = *(const float4*)&b[lane * 4];
    float4 xx = *(const float4*)&x[(size_t)gw * DD + lane * 4];

    float4 r;
    r.x = xx.x + dx * rs * gg.x + bb.x;
    r.y = xx.y + dy * rs * gg.y + bb.y;
    r.z = xx.z + dz * rs * gg.z + bb.z;
    r.w = xx.w + dw * rs * gg.w + bb.w;
    *(float4*)&outp[(size_t)gw * DD + lane * 4] = r;
}

// ---------------- launch ----------------
extern "C" void kernel_launch(void* const* d_in, const int* in_sizes, int n_in,
                              void* d_out, int out_size) {
    const void*  eidx      = d_in[0];
    const float* x         = (const float*)d_in[1];
    const float* edge_attr = (const float*)d_in[2];
    const float* Wq = (const float*)d_in[3],  *bq = (const float*)d_in[4];
    const float* Wk = (const float*)d_in[5],  *bk = (const float*)d_in[6];
    const float* Wv = (const float*)d_in[7],  *bv = (const float*)d_in[8];
    const float* We = (const float*)d_in[9];
    const float* Wskip = (const float*)d_in[10], *bskip = (const float*)d_in[11];
    const float* W1 = (const float*)d_in[12], *b1 = (const float*)d_in[13];
    const float* W2 = (const float*)d_in[14], *b2 = (const float*)d_in[15];
    const float* g1 = (const float*)d_in[16], *be1 = (const float*)d_in[17];
    const float* g2 = (const float*)d_in[18], *be2 = (const float*)d_in[19];
    float* out = (float*)d_out;

    int N = in_sizes[1] / DD;   // 100000
    int E = in_sizes[2] / DD;   // 600000

    float *pQ, *pK, *pV, *pSK, *pAGG, *pH, *pDen;
    cudaGetSymbolAddress((void**)&pQ,   g_Q);
    cudaGetSymbolAddress((void**)&pK,   g_K);
    cudaGetSymbolAddress((void**)&pV,   g_V);
    cudaGetSymbolAddress((void**)&pSK,  g_SKIP);
    cudaGetSymbolAddress((void**)&pAGG, g_AGG);
    cudaGetSymbolAddress((void**)&pH,   g_H);
    cudaGetSymbolAddress((void**)&pDen, g_den);

    cudaFuncSetAttribute(mma_gemm_kernel, cudaFuncAttributeMaxDynamicSharedMemorySize,
                         GEMM_SMEM);
    cudaFuncSetAttribute(fused_edge_kernel, cudaFuncAttributeMaxDynamicSharedMemorySize,
                         FUSED_SMEM);
    cudaFuncSetAttribute(ffn_kernel, cudaFuncAttributeMaxDynamicSharedMemorySize,
                         FFN_SMEM);

    detect_idx_kernel<<<1, 32>>>((const long long*)eidx, E, N);
    zero_kernel<<<1024, 256>>>(pDen, (size_t)N * 8, pAGG, (size_t)N * DD);

    // node projections
    int nb_node = (N + 63) / 64;
    mma_gemm_kernel<<<nb_node, 256, GEMM_SMEM>>>(x, N, 4,
        Wq, Wk, Wv, Wskip, bq, bk, bv, bskip, pQ, pK, pV, pSK);

    // fused edge GEMM + attention (512 threads, prefetch)
    int ntiles = (E + 63) / 64;
    int nb_fused = (ntiles + TPC - 1) / TPC;
    fused_edge_kernel<<<nb_fused, 512, FUSED_SMEM>>>(edge_attr, We, pQ, pK, pV,
                                                     eidx, E, pDen, pAGG);

    // h = x + LN(AGG/den + skip)
    int nbw = (N + 7) / 8;
    postln1_kernel<<<nbw, 256>>>(x, pAGG, pSK, pDen, g1, be1, pH, N);

    // fused FFN + final LN + residual -> out
    ffn_kernel<<<nb_node, 256, FFN_SMEM>>>(pH, W1, b1, W2, b2, g2, be2, out, N);
}

// round 11
// speedup vs baseline: 1.3270x; 1.0135x over previous
#include <cuda_runtime.h>
#include <cstdint>
#include <cstddef>

// Problem constants
#define NN 100000
#define EE 600000
#define DD 128

// ---------------- scratch ----------------
__device__ float g_Q   [(size_t)NN * DD];
__device__ float g_K   [(size_t)NN * DD];
__device__ float g_V   [(size_t)NN * DD];
__device__ float g_SKIP[(size_t)NN * DD];
__device__ float g_AGG [(size_t)NN * DD];
__device__ float g_H   [(size_t)NN * DD];
__device__ float g_den [(size_t)NN * 8];
__device__ int   g_is64;

// ---------------- tf32 helpers ----------------
__device__ __forceinline__ uint32_t f2tf32(float v) {
    uint32_t r;
    asm("cvt.rna.tf32.f32 %0, %1;" : "=r"(r) : "f"(v));
    return r;
}
__device__ __forceinline__ void mma_tf32(float& d0, float& d1, float& d2, float& d3,
                                         uint32_t a0, uint32_t a1, uint32_t a2, uint32_t a3,
                                         uint32_t b0, uint32_t b1) {
    asm volatile(
        "mma.sync.aligned.m16n8k8.row.col.f32.tf32.tf32.f32 "
        "{%0,%1,%2,%3}, {%4,%5,%6,%7}, {%8,%9}, {%0,%1,%2,%3};"
        : "+f"(d0), "+f"(d1), "+f"(d2), "+f"(d3)
        : "r"(a0), "r"(a1), "r"(a2), "r"(a3), "r"(b0), "r"(b1));
}

#define AS_STRIDE 132
#define WS_STRIDE 136
#define AS_ELEMS  (64 * AS_STRIDE)                 // 8448
#define WS_ELEMS  (128 * WS_STRIDE)                // 17408
#define GEMM_SMEM ((AS_ELEMS + WS_ELEMS) * 4)      // 103424 -> 2 CTAs/SM
#define FFN_SMEM  GEMM_SMEM
#define FUSED_SMEM (GEMM_SMEM + 64 * 2 * 4)

#define TPC 8   // 64-edge tiles per CTA in fused edge kernel

__device__ __forceinline__ int load_idx(const void* p, long long i, int is64) {
    if (is64) return (int)((const long long*)p)[i];
    return ((const int*)p)[i];
}

// ---------------- node projections, 512 threads (Q,K,V,SKIP share staged x) ----------------
// Warp tile: 16 rows x 32 cols (wr = wid&3, wc = wid>>2).
__global__ void __launch_bounds__(512, 2)
proj_kernel(const float* __restrict__ A, int M,
            const float* Wg0, const float* Wg1, const float* Wg2, const float* Wg3,
            const float* bg0, const float* bg1, const float* bg2, const float* bg3,
            float* og0, float* og1, float* og2, float* og3) {
    extern __shared__ uint32_t sm[];
    uint32_t* As = sm;
    uint32_t* Ws = sm + AS_ELEMS;

    int tid = threadIdx.x;
    int wid = tid >> 5;
    int lane = tid & 31;
    int row0 = blockIdx.x * 64;

    const float* Wp[4] = {Wg0, Wg1, Wg2, Wg3};
    const float* Bp[4] = {bg0, bg1, bg2, bg3};
    float*       Op[4] = {og0, og1, og2, og3};

    // stage A tile (2048 float4 / 512 = 4 iters)
#pragma unroll
    for (int it = 0; it < 4; it++) {
        int idx = it * 512 + tid;
        int r = idx >> 5, c4 = idx & 31;
        float4 v = make_float4(0.f, 0.f, 0.f, 0.f);
        if (row0 + r < M) v = ((const float4*)(A + (size_t)(row0 + r) * DD))[c4];
        uint4 t = make_uint4(f2tf32(v.x), f2tf32(v.y), f2tf32(v.z), f2tf32(v.w));
        *(uint4*)&As[r * AS_STRIDE + c4 * 4] = t;
    }

    int wr = wid & 3, wc = wid >> 2;
    int qid = lane >> 2, qln = lane & 3;

    for (int w = 0; w < 4; w++) {
        __syncthreads();
        const float* Wgp = Wp[w];
#pragma unroll
        for (int it = 0; it < 8; it++) {
            int idx = it * 512 + tid;
            int k = idx >> 5, c4 = idx & 31;
            float4 v = ((const float4*)(Wgp + (size_t)k * DD))[c4];
            uint4 t = make_uint4(f2tf32(v.x), f2tf32(v.y), f2tf32(v.z), f2tf32(v.w));
            *(uint4*)&Ws[k * WS_STRIDE + c4 * 4] = t;
        }
        __syncthreads();

        float acc[4][4];
#pragma unroll
        for (int nt = 0; nt < 4; nt++)
#pragma unroll
            for (int j = 0; j < 4; j++) acc[nt][j] = 0.f;

#pragma unroll
        for (int ks = 0; ks < 16; ks++) {
            int k0 = ks * 8;
            const uint32_t* ap = &As[(wr * 16 + qid) * AS_STRIDE + k0 + qln];
            uint32_t a0 = ap[0];
            uint32_t a2 = ap[4];
            uint32_t a1 = ap[8 * AS_STRIDE];
            uint32_t a3 = ap[8 * AS_STRIDE + 4];
#pragma unroll
            for (int nt = 0; nt < 4; nt++) {
                int n0 = wc * 32 + nt * 8;
                uint32_t b0 = Ws[(k0 + qln) * WS_STRIDE + n0 + qid];
                uint32_t b1 = Ws[(k0 + 4 + qln) * WS_STRIDE + n0 + qid];
                mma_tf32(acc[nt][0], acc[nt][1], acc[nt][2], acc[nt][3],
                         a0, a1, a2, a3, b0, b1);
            }
        }

        const float* bias = Bp[w];
        float* outp = Op[w];
#pragma unroll
        for (int nt = 0; nt < 4; nt++) {
            int col = wc * 32 + nt * 8 + qln * 2;
            float b0v = bias[col], b1v = bias[col + 1];
            int r = row0 + wr * 16 + qid;
            if (r < M)
                *(float2*)&outp[(size_t)r * DD + col] =
                    make_float2(acc[nt][0] + b0v, acc[nt][1] + b1v);
            if (r + 8 < M)
                *(float2*)&outp[(size_t)(r + 8) * DD + col] =
                    make_float2(acc[nt][2] + b0v, acc[nt][3] + b1v);
        }
    }
}

// ---------------- FUSED: edge GEMM + attention, 512 threads (R10 proven) ----------------
__global__ void __launch_bounds__(512, 2)
fused_edge_kernel(const float* __restrict__ EA, const float* __restrict__ We,
                  const float* __restrict__ Q, const float* __restrict__ K,
                  const float* __restrict__ V, const void* __restrict__ eidx,
                  int E, float* __restrict__ denom, float* __restrict__ AGG) {
    extern __shared__ uint32_t sm[];
    uint32_t* Ws  = sm;                         // [128][WS_STRIDE]
    uint32_t* As  = sm + WS_ELEMS;              // [64][AS_STRIDE], reused as Ef
    int* ssrc = (int*)(sm + WS_ELEMS + AS_ELEMS);
    int* sdst = ssrc + 64;

    int tid = threadIdx.x;
    int wid = tid >> 5;
    int lane = tid & 31;
    int is64 = g_is64;

    // stage We once
#pragma unroll
    for (int it = 0; it < 8; it++) {
        int idx = it * 512 + tid;
        int k = idx >> 5, c4 = idx & 31;
        float4 v = ((const float4*)(We + (size_t)k * DD))[c4];
        uint4 t = make_uint4(f2tf32(v.x), f2tf32(v.y), f2tf32(v.z), f2tf32(v.w));
        *(uint4*)&Ws[k * WS_STRIDE + c4 * 4] = t;
    }

    int wr = wid & 3;
    int wc = wid >> 2;
    int qid = lane >> 2, qln = lane & 3;

    int ntiles = (E + 63) >> 6;
    int t_end = blockIdx.x * TPC + TPC;
    if (t_end > ntiles) t_end = ntiles;

    for (int t = blockIdx.x * TPC; t < t_end; t++) {
        int e0 = t << 6;
        __syncthreads();

        // stage edge_attr tile (tf32)
#pragma unroll
        for (int it = 0; it < 4; it++) {
            int idx = it * 512 + tid;
            int r = idx >> 5, c4 = idx & 31;
            float4 v = make_float4(0.f, 0.f, 0.f, 0.f);
            if (e0 + r < E) v = ((const float4*)(EA + (size_t)(e0 + r) * DD))[c4];
            uint4 tt = make_uint4(f2tf32(v.x), f2tf32(v.y), f2tf32(v.z), f2tf32(v.w));
            *(uint4*)&As[r * AS_STRIDE + c4 * 4] = tt;
        }
        if (tid < 64) {
            long long ee = (long long)(e0 + tid);
            int ok = (e0 + tid) < E;
            ssrc[tid] = ok ? load_idx(eidx, ee, is64) : 0;
            sdst[tid] = ok ? load_idx(eidx, (long long)E + ee, is64) : 0;
        }
        __syncthreads();

        // L2 prefetch of this tile's q/k/v gather rows
        {
            int le   = wid * 4 + (lane >> 3);
            int part = (lane & 3) * 32;
            int psrc = ssrc[le], pdst = sdst[le];
            const float* qb = Q + (size_t)pdst * DD + part;
            const float* kb = K + (size_t)psrc * DD + part;
            const float* vb = V + (size_t)psrc * DD + part;
            asm volatile("prefetch.global.L2 [%0];" :: "l"(qb));
            asm volatile("prefetch.global.L2 [%0];" :: "l"(kb));
            asm volatile("prefetch.global.L2 [%0];" :: "l"(vb));
        }

        // MMA: Ef_tile[64,128] = A_tile @ We
        float acc[4][4];
#pragma unroll
        for (int nt = 0; nt < 4; nt++)
#pragma unroll
            for (int j = 0; j < 4; j++) acc[nt][j] = 0.f;

#pragma unroll
        for (int ks = 0; ks < 16; ks++) {
            int k0 = ks * 8;
            const uint32_t* ap = &As[(wr * 16 + qid) * AS_STRIDE + k0 + qln];
            uint32_t a0 = ap[0];
            uint32_t a2 = ap[4];
            uint32_t a1 = ap[8 * AS_STRIDE];
            uint32_t a3 = ap[8 * AS_STRIDE + 4];
#pragma unroll
            for (int nt = 0; nt < 4; nt++) {
                int n0 = wc * 32 + nt * 8;
                uint32_t b0 = Ws[(k0 + qln) * WS_STRIDE + n0 + qid];
                uint32_t b1 = Ws[(k0 + 4 + qln) * WS_STRIDE + n0 + qid];
                mma_tf32(acc[nt][0], acc[nt][1], acc[nt][2], acc[nt][3],
                         a0, a1, a2, a3, b0, b1);
            }
        }
        __syncthreads();

        // Ef tile -> smem (f32, reuse As)
        float* Es = (float*)As;
#pragma unroll
        for (int nt = 0; nt < 4; nt++) {
            int col = wc * 32 + nt * 8 + qln * 2;
            int r = wr * 16 + qid;
            *(float2*)&Es[r * AS_STRIDE + col] =
                make_float2(acc[nt][0], acc[nt][1]);
            *(float2*)&Es[(r + 8) * AS_STRIDE + col] =
                make_float2(acc[nt][2], acc[nt][3]);
        }
        __syncthreads();

        // attention: warp wid handles edges e0 + wid*4 .. +3
        for (int i = 0; i < 4; i++) {
            int le = wid * 4 + i;
            bool ok = (e0 + le) < E;
            int src = ssrc[le], dst = sdst[le];

            float4 e4 = *(const float4*)&Es[le * AS_STRIDE + lane * 4];
            float4 q4 = *(const float4*)&Q[(size_t)dst * DD + lane * 4];
            float4 k4 = *(const float4*)&K[(size_t)src * DD + lane * 4];

            float p = q4.x * (k4.x + e4.x) + q4.y * (k4.y + e4.y) +
                      q4.z * (k4.z + e4.z) + q4.w * (k4.w + e4.w);
            p += __shfl_xor_sync(0xffffffffu, p, 1);
            p += __shfl_xor_sync(0xffffffffu, p, 2);

            float ex = expf(p * 0.25f);
            float4 v4 = *(const float4*)&V[(size_t)src * DD + lane * 4];
            if (ok) {
                if ((lane & 3) == 0)
                    atomicAdd(&denom[(size_t)dst * 8 + (lane >> 2)], ex);
                float m0 = ex * (v4.x + e4.x);
                float m1 = ex * (v4.y + e4.y);
                float m2 = ex * (v4.z + e4.z);
                float m3 = ex * (v4.w + e4.w);
                float* o = &AGG[(size_t)dst * DD + lane * 4];
                asm volatile("red.global.add.v4.f32 [%0], {%1,%2,%3,%4};"
                             :: "l"(o), "f"(m0), "f"(m1), "f"(m2), "f"(m3) : "memory");
            }
        }
    }
}

// ---------------- FUSED FFN, 512 threads: out = H + LN(silu(H@W1+b1)@W2 + b2) ----------------
__global__ void __launch_bounds__(512, 2)
ffn_kernel(const float* __restrict__ H,
           const float* __restrict__ W1, const float* __restrict__ b1,
           const float* __restrict__ W2, const float* __restrict__ b2,
           const float* __restrict__ g, const float* __restrict__ be,
           float* __restrict__ outp, int M) {
    extern __shared__ uint32_t sm[];
    uint32_t* As = sm;
    uint32_t* Ws = sm + AS_ELEMS;

    int tid = threadIdx.x;
    int wid = tid >> 5;
    int lane = tid & 31;
    int row0 = blockIdx.x * 64;

    // stage H tile (tf32) + W1
#pragma unroll
    for (int it = 0; it < 4; it++) {
        int idx = it * 512 + tid;
        int r = idx >> 5, c4 = idx & 31;
        float4 v = make_float4(0.f, 0.f, 0.f, 0.f);
        if (row0 + r < M) v = ((const float4*)(H + (size_t)(row0 + r) * DD))[c4];
        uint4 t = make_uint4(f2tf32(v.x), f2tf32(v.y), f2tf32(v.z), f2tf32(v.w));
        *(uint4*)&As[r * AS_STRIDE + c4 * 4] = t;
    }
#pragma unroll
    for (int it = 0; it < 8; it++) {
        int idx = it * 512 + tid;
        int k = idx >> 5, c4 = idx & 31;
        float4 v = ((const float4*)(W1 + (size_t)k * DD))[c4];
        uint4 t = make_uint4(f2tf32(v.x), f2tf32(v.y), f2tf32(v.z), f2tf32(v.w));
        *(uint4*)&Ws[k * WS_STRIDE + c4 * 4] = t;
    }
    __syncthreads();

    int wr = wid & 3, wc = wid >> 2;
    int qid = lane >> 2, qln = lane & 3;

    // ---- MMA 1: T = H @ W1 ----
    float acc[4][4];
#pragma unroll
    for (int nt = 0; nt < 4; nt++)
#pragma unroll
        for (int j = 0; j < 4; j++) acc[nt][j] = 0.f;

#pragma unroll
    for (int ks = 0; ks < 16; ks++) {
        int k0 = ks * 8;
        const uint32_t* ap = &As[(wr * 16 + qid) * AS_STRIDE + k0 + qln];
        uint32_t a0 = ap[0];
        uint32_t a2 = ap[4];
        uint32_t a1 = ap[8 * AS_STRIDE];
        uint32_t a3 = ap[8 * AS_STRIDE + 4];
#pragma unroll
        for (int nt = 0; nt < 4; nt++) {
            int n0 = wc * 32 + nt * 8;
            uint32_t b0 = Ws[(k0 + qln) * WS_STRIDE + n0 + qid];
            uint32_t b1v = Ws[(k0 + 4 + qln) * WS_STRIDE + n0 + qid];
            mma_tf32(acc[nt][0], acc[nt][1], acc[nt][2], acc[nt][3],
                     a0, a1, a2, a3, b0, b1v);
        }
    }
    __syncthreads();

    // T1 = silu(acc + b1) -> As (tf32); stage W2 -> Ws
#pragma unroll
    for (int nt = 0; nt < 4; nt++) {
        int col = wc * 32 + nt * 8 + qln * 2;
        float c0 = b1[col], c1 = b1[col + 1];
        int r = wr * 16 + qid;
        float o0 = acc[nt][0] + c0;
        float o1 = acc[nt][1] + c1;
        float o2 = acc[nt][2] + c0;
        float o3 = acc[nt][3] + c1;
        o0 = o0 / (1.f + expf(-o0));
        o1 = o1 / (1.f + expf(-o1));
        o2 = o2 / (1.f + expf(-o2));
        o3 = o3 / (1.f + expf(-o3));
        As[r * AS_STRIDE + col]           = f2tf32(o0);
        As[r * AS_STRIDE + col + 1]       = f2tf32(o1);
        As[(r + 8) * AS_STRIDE + col]     = f2tf32(o2);
        As[(r + 8) * AS_STRIDE + col + 1] = f2tf32(o3);
    }
#pragma unroll
    for (int it = 0; it < 8; it++) {
        int idx = it * 512 + tid;
        int k = idx >> 5, c4 = idx & 31;
        float4 v = ((const float4*)(W2 + (size_t)k * DD))[c4];
        uint4 t = make_uint4(f2tf32(v.x), f2tf32(v.y), f2tf32(v.z), f2tf32(v.w));
        *(uint4*)&Ws[k * WS_STRIDE + c4 * 4] = t;
    }
    __syncthreads();

    // ---- MMA 2: F = T1 @ W2 ----
#pragma unroll
    for (int nt = 0; nt < 4; nt++)
#pragma unroll
        for (int j = 0; j < 4; j++) acc[nt][j] = 0.f;

#pragma unroll
    for (int ks = 0; ks < 16; ks++) {
        int k0 = ks * 8;
        const uint32_t* ap = &As[(wr * 16 + qid) * AS_STRIDE + k0 + qln];
        uint32_t a0 = ap[0];
        uint32_t a2 = ap[4];
        uint32_t a1 = ap[8 * AS_STRIDE];
        uint32_t a3 = ap[8 * AS_STRIDE + 4];
#pragma unroll
        for (int nt = 0; nt < 4; nt++) {
            int n0 = wc * 32 + nt * 8;
            uint32_t b0 = Ws[(k0 + qln) * WS_STRIDE + n0 + qid];
            uint32_t b1v = Ws[(k0 + 4 + qln) * WS_STRIDE + n0 + qid];
            mma_tf32(acc[nt][0], acc[nt][1], acc[nt][2], acc[nt][3],
                     a0, a1, a2, a3, b0, b1v);
        }
    }
    __syncthreads();

    // F2 tile (+b2) -> Ws smem (f32)
    float* Es = (float*)Ws;
#pragma unroll
    for (int nt = 0; nt < 4; nt++) {
        int col = wc * 32 + nt * 8 + qln * 2;
        float c0 = b2[col], c1 = b2[col + 1];
        int r = wr * 16 + qid;
        *(float2*)&Es[r * AS_STRIDE + col] =
            make_float2(acc[nt][0] + c0, acc[nt][1] + c1);
        *(float2*)&Es[(r + 8) * AS_STRIDE + col] =
            make_float2(acc[nt][2] + c0, acc[nt][3] + c1);
    }
    __syncthreads();

    // LN + residual: warp wid handles rows wid*4 .. +3
#pragma unroll
    for (int i = 0; i < 4; i++) {
        int r = wid * 4 + i;
        float4 o = *(float4*)&Es[r * AS_STRIDE + lane * 4];

        float sum = o.x + o.y + o.z + o.w;
#pragma unroll
        for (int off = 16; off >= 1; off >>= 1)
            sum += __shfl_xor_sync(0xffffffffu, sum, off);
        float mu = sum * (1.0f / 128.0f);

        float dx = o.x - mu, dy = o.y - mu, dz = o.z - mu, dw = o.w - mu;
        float ss = dx * dx + dy * dy + dz * dz + dw * dw;
#pragma unroll
        for (int off = 16; off >= 1; off >>= 1)
            ss += __shfl_xor_sync(0xffffffffu, ss, off);
        float rs = rsqrtf(ss * (1.0f / 128.0f) + 1e-5f);

        if (row0 + r < M) {
            float4 gg = *(const float4*)&g[lane * 4];
            float4 bb = *(const float4*)&be[lane * 4];
            float4 hh = *(const float4*)&H[(size_t)(row0 + r) * DD + lane * 4];
            float4 rr;
            rr.x = hh.x + dx * rs * gg.x + bb.x;
            rr.y = hh.y + dy * rs * gg.y + bb.y;
            rr.z = hh.z + dz * rs * gg.z + bb.z;
            rr.w = hh.w + dw * rs * gg.w + bb.w;
            *(float4*)&outp[(size_t)(row0 + r) * DD + lane * 4] = rr;
        }
    }
}

// ---------------- edge index dtype detection ----------------
__global__ void detect_idx_kernel(const long long* __restrict__ p, int E, int N) {
    if (threadIdx.x == 0 && blockIdx.x == 0) {
        int ok64 = 1;
        int n = (E < 64) ? E : 64;
        for (int i = 0; i < n; i++) {
            long long v = p[i];
            if (v < 0 || v >= (long long)N) { ok64 = 0; break; }
        }
        g_is64 = ok64;
    }
}

// ---------------- zero accumulators (vectorized) ----------------
__global__ void zero_kernel(float4* __restrict__ a, size_t na4,
                            float4* __restrict__ b, size_t nb4) {
    size_t i = (size_t)blockIdx.x * blockDim.x + threadIdx.x;
    size_t stride = (size_t)gridDim.x * blockDim.x;
    float4 z = make_float4(0.f, 0.f, 0.f, 0.f);
    for (size_t j = i; j < na4; j += stride) a[j] = z;
    for (size_t j = i; j < nb4; j += stride) b[j] = z;
}

// ---------------- h = x + LN(AGG/den + SKIP) ----------------
__global__ void postln1_kernel(const float* __restrict__ x, const float* __restrict__ AGG,
                               const float* __restrict__ SKIP, const float* __restrict__ den,
                               const float* __restrict__ g, const float* __restrict__ b,
                               float* __restrict__ outp, int M) {
    long long gw = ((long long)blockIdx.x * blockDim.x + threadIdx.x) >> 5;
    int lane = threadIdx.x & 31;
    if (gw >= M) return;

    float dh = den[(size_t)gw * 8 + (lane >> 2)];
    float inv = 1.0f / (dh + 1e-16f);

    float4 o = *(const float4*)&AGG[(size_t)gw * DD + lane * 4];
    float4 s = *(const float4*)&SKIP[(size_t)gw * DD + lane * 4];
    o.x = o.x * inv + s.x;
    o.y = o.y * inv + s.y;
    o.z = o.z * inv + s.z;
    o.w = o.w * inv + s.w;

    float sum = o.x + o.y + o.z + o.w;
#pragma unroll
    for (int off = 16; off >= 1; off >>= 1) sum += __shfl_xor_sync(0xffffffffu, sum, off);
    float mu = sum * (1.0f / 128.0f);

    float dx = o.x - mu, dy = o.y - mu, dz = o.z - mu, dw = o.w - mu;
    float ss = dx * dx + dy * dy + dz * dz + dw * dw;
#pragma unroll
    for (int off = 16; off >= 1; off >>= 1) ss += __shfl_xor_sync(0xffffffffu, ss, off);
    float rs = rsqrtf(ss * (1.0f / 128.0f) + 1e-5f);

    float4 gg = *(const float4*)&g[lane * 4];
    float4 bb = *(const float4*)&b[lane * 4];
    float4 xx = *(const float4*)&x[(size_t)gw * DD + lane * 4];

    float4 r;
    r.x = xx.x + dx * rs * gg.x + bb.x;
    r.y = xx.y + dy * rs * gg.y + bb.y;
    r.z = xx.z + dz * rs * gg.z + bb.z;
    r.w = xx.w + dw * rs * gg.w + bb.w;
    *(float4*)&outp[(size_t)gw * DD + lane * 4] = r;
}

// ---------------- launch ----------------
extern "C" void kernel_launch(void* const* d_in, const int* in_sizes, int n_in,
                              void* d_out, int out_size) {
    const void*  eidx      = d_in[0];
    const float* x         = (const float*)d_in[1];
    const float* edge_attr = (const float*)d_in[2];
    const float* Wq = (const float*)d_in[3],  *bq = (const float*)d_in[4];
    const float* Wk = (const float*)d_in[5],  *bk = (const float*)d_in[6];
    const float* Wv = (const float*)d_in[7],  *bv = (const float*)d_in[8];
    const float* We = (const float*)d_in[9];
    const float* Wskip = (const float*)d_in[10], *bskip = (const float*)d_in[11];
    const float* W1 = (const float*)d_in[12], *b1 = (const float*)d_in[13];
    const float* W2 = (const float*)d_in[14], *b2 = (const float*)d_in[15];
    const float* g1 = (const float*)d_in[16], *be1 = (const float*)d_in[17];
    const float* g2 = (const float*)d_in[18], *be2 = (const float*)d_in[19];
    float* out = (float*)d_out;

    int N = in_sizes[1] / DD;   // 100000
    int E = in_sizes[2] / DD;   // 600000

    float *pQ, *pK, *pV, *pSK, *pAGG, *pH, *pDen;
    cudaGetSymbolAddress((void**)&pQ,   g_Q);
    cudaGetSymbolAddress((void**)&pK,   g_K);
    cudaGetSymbolAddress((void**)&pV,   g_V);
    cudaGetSymbolAddress((void**)&pSK,  g_SKIP);
    cudaGetSymbolAddress((void**)&pAGG, g_AGG);
    cudaGetSymbolAddress((void**)&pH,   g_H);
    cudaGetSymbolAddress((void**)&pDen, g_den);

    cudaFuncSetAttribute(proj_kernel, cudaFuncAttributeMaxDynamicSharedMemorySize,
                         GEMM_SMEM);
    cudaFuncSetAttribute(fused_edge_kernel, cudaFuncAttributeMaxDynamicSharedMemorySize,
                         FUSED_SMEM);
    cudaFuncSetAttribute(ffn_kernel, cudaFuncAttributeMaxDynamicSharedMemorySize,
                         FFN_SMEM);

    detect_idx_kernel<<<1, 32>>>((const long long*)eidx, E, N);
    zero_kernel<<<1024, 256>>>((float4*)pDen, (size_t)N * 2,
                               (float4*)pAGG, (size_t)N * 32);

    // node projections (512 threads)
    int nb_node = (N + 63) / 64;
    proj_kernel<<<nb_node, 512, GEMM_SMEM>>>(x, N,
        Wq, Wk, Wv, Wskip, bq, bk, bv, bskip, pQ, pK, pV, pSK);

    // fused edge GEMM + attention (512 threads, prefetch)
    int ntiles = (E + 63) / 64;
    int nb_fused = (ntiles + TPC - 1) / TPC;
    fused_edge_kernel<<<nb_fused, 512, FUSED_SMEM>>>(edge_attr, We, pQ, pK, pV,
                                                     eidx, E, pDen, pAGG);

    // h = x + LN(AGG/den + skip)
    int nbw = (N + 7) / 8;
    postln1_kernel<<<nbw, 256>>>(x, pAGG, pSK, pDen, g1, be1, pH, N);

    // fused FFN + final LN + residual -> out (512 threads)
    ffn_kernel<<<nb_node, 512, FFN_SMEM>>>(pH, W1, b1, W2, b2, g2, be2, out, N);
}

// round 12
// speedup vs baseline: 1.3577x; 1.0231x over previous
#include <cuda_runtime.h>
#include <cstdint>
#include <cstddef>

// Problem constants
#define NN 100000
#define EE 600000
#define DD 128

// ---------------- scratch ----------------
__device__ float g_Q   [(size_t)NN * DD];
__device__ float g_K   [(size_t)NN * DD];
__device__ float g_V   [(size_t)NN * DD];
__device__ float g_SKIP[(size_t)NN * DD];
__device__ float g_AGG [(size_t)NN * DD];
__device__ float g_H   [(size_t)NN * DD];
__device__ float g_den [(size_t)NN * 8];
__device__ int   g_is64;

// ---------------- tf32 helpers ----------------
__device__ __forceinline__ uint32_t f2tf32(float v) {
    uint32_t r;
    asm("cvt.rna.tf32.f32 %0, %1;" : "=r"(r) : "f"(v));
    return r;
}
__device__ __forceinline__ void mma_tf32(float& d0, float& d1, float& d2, float& d3,
                                         uint32_t a0, uint32_t a1, uint32_t a2, uint32_t a3,
                                         uint32_t b0, uint32_t b1) {
    asm volatile(
        "mma.sync.aligned.m16n8k8.row.col.f32.tf32.tf32.f32 "
        "{%0,%1,%2,%3}, {%4,%5,%6,%7}, {%8,%9}, {%0,%1,%2,%3};"
        : "+f"(d0), "+f"(d1), "+f"(d2), "+f"(d3)
        : "r"(a0), "r"(a1), "r"(a2), "r"(a3), "r"(b0), "r"(b1));
}

#define AS_STRIDE 132
#define WS_STRIDE 136
#define AS_ELEMS  (64 * AS_STRIDE)                 // 8448
#define WS_ELEMS  (128 * WS_STRIDE)                // 17408
#define GEMM_SMEM ((AS_ELEMS + WS_ELEMS) * 4)      // 103424 -> 2 CTAs/SM
#define FFN_SMEM  GEMM_SMEM
#define FUSED_SMEM (GEMM_SMEM + 64 * 2 * 4)

#define TPC 8   // 64-edge tiles per CTA in fused edge kernel

__device__ __forceinline__ int load_idx(const void* p, long long i, int is64) {
    if (is64) return (int)((const long long*)p)[i];
    return ((const int*)p)[i];
}

// ---------------- node projections, 512 threads; also zeroes AGG/den ----------------
__global__ void __launch_bounds__(512, 2)
proj_kernel(const float* __restrict__ A, int M,
            const float* Wg0, const float* Wg1, const float* Wg2, const float* Wg3,
            const float* bg0, const float* bg1, const float* bg2, const float* bg3,
            float* og0, float* og1, float* og2, float* og3,
            float* __restrict__ AGG, float* __restrict__ den) {
    extern __shared__ uint32_t sm[];
    uint32_t* As = sm;
    uint32_t* Ws = sm + AS_ELEMS;

    int tid = threadIdx.x;
    int wid = tid >> 5;
    int lane = tid & 31;
    int row0 = blockIdx.x * 64;

    const float* Wp[4] = {Wg0, Wg1, Wg2, Wg3};
    const float* Bp[4] = {bg0, bg1, bg2, bg3};
    float*       Op[4] = {og0, og1, og2, og3};

    // zero this block's AGG rows + den entries (complete before fused kernel
    // by stream ordering)
    {
        float4 z = make_float4(0.f, 0.f, 0.f, 0.f);
#pragma unroll
        for (int it = 0; it < 4; it++) {
            int idx = it * 512 + tid;
            int r = idx >> 5, c4 = idx & 31;
            if (row0 + r < M) ((float4*)(AGG + (size_t)(row0 + r) * DD))[c4] = z;
        }
        int r = tid >> 3, hh = tid & 7;
        if (row0 + r < M) den[(size_t)(row0 + r) * 8 + hh] = 0.f;
    }

    // stage A tile (2048 float4 / 512 = 4 iters)
#pragma unroll
    for (int it = 0; it < 4; it++) {
        int idx = it * 512 + tid;
        int r = idx >> 5, c4 = idx & 31;
        float4 v = make_float4(0.f, 0.f, 0.f, 0.f);
        if (row0 + r < M) v = ((const float4*)(A + (size_t)(row0 + r) * DD))[c4];
        uint4 t = make_uint4(f2tf32(v.x), f2tf32(v.y), f2tf32(v.z), f2tf32(v.w));
        *(uint4*)&As[r * AS_STRIDE + c4 * 4] = t;
    }

    int wr = wid & 3, wc = wid >> 2;
    int qid = lane >> 2, qln = lane & 3;

    for (int w = 0; w < 4; w++) {
        __syncthreads();
        const float* Wgp = Wp[w];
#pragma unroll
        for (int it = 0; it < 8; it++) {
            int idx = it * 512 + tid;
            int k = idx >> 5, c4 = idx & 31;
            float4 v = ((const float4*)(Wgp + (size_t)k * DD))[c4];
            uint4 t = make_uint4(f2tf32(v.x), f2tf32(v.y), f2tf32(v.z), f2tf32(v.w));
            *(uint4*)&Ws[k * WS_STRIDE + c4 * 4] = t;
        }
        __syncthreads();

        float acc[4][4];
#pragma unroll
        for (int nt = 0; nt < 4; nt++)
#pragma unroll
            for (int j = 0; j < 4; j++) acc[nt][j] = 0.f;

#pragma unroll
        for (int ks = 0; ks < 16; ks++) {
            int k0 = ks * 8;
            const uint32_t* ap = &As[(wr * 16 + qid) * AS_STRIDE + k0 + qln];
            uint32_t a0 = ap[0];
            uint32_t a2 = ap[4];
            uint32_t a1 = ap[8 * AS_STRIDE];
            uint32_t a3 = ap[8 * AS_STRIDE + 4];
#pragma unroll
            for (int nt = 0; nt < 4; nt++) {
                int n0 = wc * 32 + nt * 8;
                uint32_t b0 = Ws[(k0 + qln) * WS_STRIDE + n0 + qid];
                uint32_t b1 = Ws[(k0 + 4 + qln) * WS_STRIDE + n0 + qid];
                mma_tf32(acc[nt][0], acc[nt][1], acc[nt][2], acc[nt][3],
                         a0, a1, a2, a3, b0, b1);
            }
        }

        const float* bias = Bp[w];
        float* outp = Op[w];
#pragma unroll
        for (int nt = 0; nt < 4; nt++) {
            int col = wc * 32 + nt * 8 + qln * 2;
            float b0v = bias[col], b1v = bias[col + 1];
            int r = row0 + wr * 16 + qid;
            if (r < M)
                *(float2*)&outp[(size_t)r * DD + col] =
                    make_float2(acc[nt][0] + b0v, acc[nt][1] + b1v);
            if (r + 8 < M)
                *(float2*)&outp[(size_t)(r + 8) * DD + col] =
                    make_float2(acc[nt][2] + b0v, acc[nt][3] + b1v);
        }
    }
}

// ---------------- FUSED: edge GEMM + attention, 512 threads (R10 proven) ----------------
__global__ void __launch_bounds__(512, 2)
fused_edge_kernel(const float* __restrict__ EA, const float* __restrict__ We,
                  const float* __restrict__ Q, const float* __restrict__ K,
                  const float* __restrict__ V, const void* __restrict__ eidx,
                  int E, float* __restrict__ denom, float* __restrict__ AGG) {
    extern __shared__ uint32_t sm[];
    uint32_t* Ws  = sm;                         // [128][WS_STRIDE]
    uint32_t* As  = sm + WS_ELEMS;              // [64][AS_STRIDE], reused as Ef
    int* ssrc = (int*)(sm + WS_ELEMS + AS_ELEMS);
    int* sdst = ssrc + 64;

    int tid = threadIdx.x;
    int wid = tid >> 5;
    int lane = tid & 31;
    int is64 = g_is64;

    // stage We once
#pragma unroll
    for (int it = 0; it < 8; it++) {
        int idx = it * 512 + tid;
        int k = idx >> 5, c4 = idx & 31;
        float4 v = ((const float4*)(We + (size_t)k * DD))[c4];
        uint4 t = make_uint4(f2tf32(v.x), f2tf32(v.y), f2tf32(v.z), f2tf32(v.w));
        *(uint4*)&Ws[k * WS_STRIDE + c4 * 4] = t;
    }

    int wr = wid & 3;
    int wc = wid >> 2;
    int qid = lane >> 2, qln = lane & 3;

    int ntiles = (E + 63) >> 6;
    int t_end = blockIdx.x * TPC + TPC;
    if (t_end > ntiles) t_end = ntiles;

    for (int t = blockIdx.x * TPC; t < t_end; t++) {
        int e0 = t << 6;
        __syncthreads();

        // stage edge_attr tile (tf32)
#pragma unroll
        for (int it = 0; it < 4; it++) {
            int idx = it * 512 + tid;
            int r = idx >> 5, c4 = idx & 31;
            float4 v = make_float4(0.f, 0.f, 0.f, 0.f);
            if (e0 + r < E) v = ((const float4*)(EA + (size_t)(e0 + r) * DD))[c4];
            uint4 tt = make_uint4(f2tf32(v.x), f2tf32(v.y), f2tf32(v.z), f2tf32(v.w));
            *(uint4*)&As[r * AS_STRIDE + c4 * 4] = tt;
        }
        if (tid < 64) {
            long long ee = (long long)(e0 + tid);
            int ok = (e0 + tid) < E;
            ssrc[tid] = ok ? load_idx(eidx, ee, is64) : 0;
            sdst[tid] = ok ? load_idx(eidx, (long long)E + ee, is64) : 0;
        }
        __syncthreads();

        // L2 prefetch of this tile's q/k/v gather rows
        {
            int le   = wid * 4 + (lane >> 3);
            int part = (lane & 3) * 32;
            int psrc = ssrc[le], pdst = sdst[le];
            const float* qb = Q + (size_t)pdst * DD + part;
            const float* kb = K + (size_t)psrc * DD + part;
            const float* vb = V + (size_t)psrc * DD + part;
            asm volatile("prefetch.global.L2 [%0];" :: "l"(qb));
            asm volatile("prefetch.global.L2 [%0];" :: "l"(kb));
            asm volatile("prefetch.global.L2 [%0];" :: "l"(vb));
        }

        // MMA: Ef_tile[64,128] = A_tile @ We
        float acc[4][4];
#pragma unroll
        for (int nt = 0; nt < 4; nt++)
#pragma unroll
            for (int j = 0; j < 4; j++) acc[nt][j] = 0.f;

#pragma unroll
        for (int ks = 0; ks < 16; ks++) {
            int k0 = ks * 8;
            const uint32_t* ap = &As[(wr * 16 + qid) * AS_STRIDE + k0 + qln];
            uint32_t a0 = ap[0];
            uint32_t a2 = ap[4];
            uint32_t a1 = ap[8 * AS_STRIDE];
            uint32_t a3 = ap[8 * AS_STRIDE + 4];
#pragma unroll
            for (int nt = 0; nt < 4; nt++) {
                int n0 = wc * 32 + nt * 8;
                uint32_t b0 = Ws[(k0 + qln) * WS_STRIDE + n0 + qid];
                uint32_t b1 = Ws[(k0 + 4 + qln) * WS_STRIDE + n0 + qid];
                mma_tf32(acc[nt][0], acc[nt][1], acc[nt][2], acc[nt][3],
                         a0, a1, a2, a3, b0, b1);
            }
        }
        __syncthreads();

        // Ef tile -> smem (f32, reuse As)
        float* Es = (float*)As;
#pragma unroll
        for (int nt = 0; nt < 4; nt++) {
            int col = wc * 32 + nt * 8 + qln * 2;
            int r = wr * 16 + qid;
            *(float2*)&Es[r * AS_STRIDE + col] =
                make_float2(acc[nt][0], acc[nt][1]);
            *(float2*)&Es[(r + 8) * AS_STRIDE + col] =
                make_float2(acc[nt][2], acc[nt][3]);
        }
        __syncthreads();

        // attention: warp wid handles edges e0 + wid*4 .. +3
        for (int i = 0; i < 4; i++) {
            int le = wid * 4 + i;
            bool ok = (e0 + le) < E;
            int src = ssrc[le], dst = sdst[le];

            float4 e4 = *(const float4*)&Es[le * AS_STRIDE + lane * 4];
            float4 q4 = *(const float4*)&Q[(size_t)dst * DD + lane * 4];
            float4 k4 = *(const float4*)&K[(size_t)src * DD + lane * 4];

            float p = q4.x * (k4.x + e4.x) + q4.y * (k4.y + e4.y) +
                      q4.z * (k4.z + e4.z) + q4.w * (k4.w + e4.w);
            p += __shfl_xor_sync(0xffffffffu, p, 1);
            p += __shfl_xor_sync(0xffffffffu, p, 2);

            float ex = expf(p * 0.25f);
            float4 v4 = *(const float4*)&V[(size_t)src * DD + lane * 4];
            if (ok) {
                if ((lane & 3) == 0)
                    atomicAdd(&denom[(size_t)dst * 8 + (lane >> 2)], ex);
                float m0 = ex * (v4.x + e4.x);
                float m1 = ex * (v4.y + e4.y);
                float m2 = ex * (v4.z + e4.z);
                float m3 = ex * (v4.w + e4.w);
                float* o = &AGG[(size_t)dst * DD + lane * 4];
                asm volatile("red.global.add.v4.f32 [%0], {%1,%2,%3,%4};"
                             :: "l"(o), "f"(m0), "f"(m1), "f"(m2), "f"(m3) : "memory");
            }
        }
    }
}

// ---------------- FUSED FFN + first LN, 512 threads ----------------
// Prologue computes h = x + LN1(AGG/den + SKIP) per row (warp-per-row LN),
// writes h to global H (f32, for the final residual) and tf32 h to smem As.
// Then: out = h + LN2(silu(h@W1+b1)@W2 + b2).
__global__ void __launch_bounds__(512, 2)
ffn_kernel(const float* __restrict__ x, const float* __restrict__ AGG,
           const float* __restrict__ SKIP, const float* __restrict__ den,
           const float* __restrict__ g1, const float* __restrict__ be1,
           float* __restrict__ H,
           const float* __restrict__ W1, const float* __restrict__ b1,
           const float* __restrict__ W2, const float* __restrict__ b2,
           const float* __restrict__ g2, const float* __restrict__ be2,
           float* __restrict__ outp, int M) {
    extern __shared__ uint32_t sm[];
    uint32_t* As = sm;
    uint32_t* Ws = sm + AS_ELEMS;

    int tid = threadIdx.x;
    int wid = tid >> 5;
    int lane = tid & 31;
    int row0 = blockIdx.x * 64;

    // ---- prologue: h = x + LN1(AGG/den + SKIP); warp wid -> rows wid*4..+3
#pragma unroll
    for (int i = 0; i < 4; i++) {
        int r = wid * 4 + i;
        int row = row0 + r;
        float4 o = make_float4(0.f, 0.f, 0.f, 0.f);
        float4 xx = o;
        float inv = 0.f;
        if (row < M) {
            float dh = den[(size_t)row * 8 + (lane >> 2)];
            inv = 1.0f / (dh + 1e-16f);
            o  = *(const float4*)&AGG[(size_t)row * DD + lane * 4];
            float4 s = *(const float4*)&SKIP[(size_t)row * DD + lane * 4];
            o.x = o.x * inv + s.x;
            o.y = o.y * inv + s.y;
            o.z = o.z * inv + s.z;
            o.w = o.w * inv + s.w;
            xx = *(const float4*)&x[(size_t)row * DD + lane * 4];
        }
        float sum = o.x + o.y + o.z + o.w;
#pragma unroll
        for (int off = 16; off >= 1; off >>= 1)
            sum += __shfl_xor_sync(0xffffffffu, sum, off);
        float mu = sum * (1.0f / 128.0f);
        float dx = o.x - mu, dy = o.y - mu, dz = o.z - mu, dw = o.w - mu;
        float ss = dx * dx + dy * dy + dz * dz + dw * dw;
#pragma unroll
        for (int off = 16; off >= 1; off >>= 1)
            ss += __shfl_xor_sync(0xffffffffu, ss, off);
        float rs = rsqrtf(ss * (1.0f / 128.0f) + 1e-5f);

        float4 gg = *(const float4*)&g1[lane * 4];
        float4 bb = *(const float4*)&be1[lane * 4];
        float4 h4;
        h4.x = xx.x + dx * rs * gg.x + bb.x;
        h4.y = xx.y + dy * rs * gg.y + bb.y;
        h4.z = xx.z + dz * rs * gg.z + bb.z;
        h4.w = xx.w + dw * rs * gg.w + bb.w;

        if (row < M)
            *(float4*)&H[(size_t)row * DD + lane * 4] = h4;
        uint4 t = make_uint4(f2tf32(h4.x), f2tf32(h4.y), f2tf32(h4.z), f2tf32(h4.w));
        *(uint4*)&As[r * AS_STRIDE + lane * 4] = t;
    }
    // stage W1
#pragma unroll
    for (int it = 0; it < 8; it++) {
        int idx = it * 512 + tid;
        int k = idx >> 5, c4 = idx & 31;
        float4 v = ((const float4*)(W1 + (size_t)k * DD))[c4];
        uint4 t = make_uint4(f2tf32(v.x), f2tf32(v.y), f2tf32(v.z), f2tf32(v.w));
        *(uint4*)&Ws[k * WS_STRIDE + c4 * 4] = t;
    }
    __syncthreads();

    int wr = wid & 3, wc = wid >> 2;
    int qid = lane >> 2, qln = lane & 3;

    // ---- MMA 1: T = h @ W1 ----
    float acc[4][4];
#pragma unroll
    for (int nt = 0; nt < 4; nt++)
#pragma unroll
        for (int j = 0; j < 4; j++) acc[nt][j] = 0.f;

#pragma unroll
    for (int ks = 0; ks < 16; ks++) {
        int k0 = ks * 8;
        const uint32_t* ap = &As[(wr * 16 + qid) * AS_STRIDE + k0 + qln];
        uint32_t a0 = ap[0];
        uint32_t a2 = ap[4];
        uint32_t a1 = ap[8 * AS_STRIDE];
        uint32_t a3 = ap[8 * AS_STRIDE + 4];
#pragma unroll
        for (int nt = 0; nt < 4; nt++) {
            int n0 = wc * 32 + nt * 8;
            uint32_t b0 = Ws[(k0 + qln) * WS_STRIDE + n0 + qid];
            uint32_t b1v = Ws[(k0 + 4 + qln) * WS_STRIDE + n0 + qid];
            mma_tf32(acc[nt][0], acc[nt][1], acc[nt][2], acc[nt][3],
                     a0, a1, a2, a3, b0, b1v);
        }
    }
    __syncthreads();

    // T1 = silu(acc + b1) -> As (tf32); stage W2 -> Ws
#pragma unroll
    for (int nt = 0; nt < 4; nt++) {
        int col = wc * 32 + nt * 8 + qln * 2;
        float c0 = b1[col], c1 = b1[col + 1];
        int r = wr * 16 + qid;
        float o0 = acc[nt][0] + c0;
        float o1 = acc[nt][1] + c1;
        float o2 = acc[nt][2] + c0;
        float o3 = acc[nt][3] + c1;
        o0 = o0 / (1.f + expf(-o0));
        o1 = o1 / (1.f + expf(-o1));
        o2 = o2 / (1.f + expf(-o2));
        o3 = o3 / (1.f + expf(-o3));
        As[r * AS_STRIDE + col]           = f2tf32(o0);
        As[r * AS_STRIDE + col + 1]       = f2tf32(o1);
        As[(r + 8) * AS_STRIDE + col]     = f2tf32(o2);
        As[(r + 8) * AS_STRIDE + col + 1] = f2tf32(o3);
    }
#pragma unroll
    for (int it = 0; it < 8; it++) {
        int idx = it * 512 + tid;
        int k = idx >> 5, c4 = idx & 31;
        float4 v = ((const float4*)(W2 + (size_t)k * DD))[c4];
        uint4 t = make_uint4(f2tf32(v.x), f2tf32(v.y), f2tf32(v.z), f2tf32(v.w));
        *(uint4*)&Ws[k * WS_STRIDE + c4 * 4] = t;
    }
    __syncthreads();

    // ---- MMA 2: F = T1 @ W2 ----
#pragma unroll
    for (int nt = 0; nt < 4; nt++)
#pragma unroll
        for (int j = 0; j < 4; j++) acc[nt][j] = 0.f;

#pragma unroll
    for (int ks = 0; ks < 16; ks++) {
        int k0 = ks * 8;
        const uint32_t* ap = &As[(wr * 16 + qid) * AS_STRIDE + k0 + qln];
        uint32_t a0 = ap[0];
        uint32_t a2 = ap[4];
        uint32_t a1 = ap[8 * AS_STRIDE];
        uint32_t a3 = ap[8 * AS_STRIDE + 4];
#pragma unroll
        for (int nt = 0; nt < 4; nt++) {
            int n0 = wc * 32 + nt * 8;
            uint32_t b0 = Ws[(k0 + qln) * WS_STRIDE + n0 + qid];
            uint32_t b1v = Ws[(k0 + 4 + qln) * WS_STRIDE + n0 + qid];
            mma_tf32(acc[nt][0], acc[nt][1], acc[nt][2], acc[nt][3],
                     a0, a1, a2, a3, b0, b1v);
        }
    }
    __syncthreads();

    // F2 tile (+b2) -> Ws smem (f32)
    float* Es = (float*)Ws;
#pragma unroll
    for (int nt = 0; nt < 4; nt++) {
        int col = wc * 32 + nt * 8 + qln * 2;
        float c0 = b2[col], c1 = b2[col + 1];
        int r = wr * 16 + qid;
        *(float2*)&Es[r * AS_STRIDE + col] =
            make_float2(acc[nt][0] + c0, acc[nt][1] + c1);
        *(float2*)&Es[(r + 8) * AS_STRIDE + col] =
            make_float2(acc[nt][2] + c0, acc[nt][3] + c1);
    }
    __syncthreads();

    // LN2 + residual: warp wid handles rows wid*4 .. +3
#pragma unroll
    for (int i = 0; i < 4; i++) {
        int r = wid * 4 + i;
        float4 o = *(float4*)&Es[r * AS_STRIDE + lane * 4];

        float sum = o.x + o.y + o.z + o.w;
#pragma unroll
        for (int off = 16; off >= 1; off >>= 1)
            sum += __shfl_xor_sync(0xffffffffu, sum, off);
        float mu = sum * (1.0f / 128.0f);

        float dx = o.x - mu, dy = o.y - mu, dz = o.z - mu, dw = o.w - mu;
        float ss = dx * dx + dy * dy + dz * dz + dw * dw;
#pragma unroll
        for (int off = 16; off >= 1; off >>= 1)
            ss += __shfl_xor_sync(0xffffffffu, ss, off);
        float rs = rsqrtf(ss * (1.0f / 128.0f) + 1e-5f);

        if (row0 + r < M) {
            float4 gg = *(const float4*)&g2[lane * 4];
            float4 bb = *(const float4*)&be2[lane * 4];
            float4 hh = *(const float4*)&H[(size_t)(row0 + r) * DD + lane * 4];
            float4 rr;
            rr.x = hh.x + dx * rs * gg.x + bb.x;
            rr.y = hh.y + dy * rs * gg.y + bb.y;
            rr.z = hh.z + dz * rs * gg.z + bb.z;
            rr.w = hh.w + dw * rs * gg.w + bb.w;
            *(float4*)&outp[(size_t)(row0 + r) * DD + lane * 4] = rr;
        }
    }
}

// ---------------- edge index dtype detection ----------------
__global__ void detect_idx_kernel(const long long* __restrict__ p, int E, int N) {
    if (threadIdx.x == 0 && blockIdx.x == 0) {
        int ok64 = 1;
        int n = (E < 64) ? E : 64;
        for (int i = 0; i < n; i++) {
            long long v = p[i];
            if (v < 0 || v >= (long long)N) { ok64 = 0; break; }
        }
        g_is64 = ok64;
    }
}

// ---------------- launch ----------------
extern "C" void kernel_launch(void* const* d_in, const int* in_sizes, int n_in,
                              void* d_out, int out_size) {
    const void*  eidx      = d_in[0];
    const float* x         = (const float*)d_in[1];
    const float* edge_attr = (const float*)d_in[2];
    const float* Wq = (const float*)d_in[3],  *bq = (const float*)d_in[4];
    const float* Wk = (const float*)d_in[5],  *bk = (const float*)d_in[6];
    const float* Wv = (const float*)d_in[7],  *bv = (const float*)d_in[8];
    const float* We = (const float*)d_in[9];
    const float* Wskip = (const float*)d_in[10], *bskip = (const float*)d_in[11];
    const float* W1 = (const float*)d_in[12], *b1 = (const float*)d_in[13];
    const float* W2 = (const float*)d_in[14], *b2 = (const float*)d_in[15];
    const float* g1 = (const float*)d_in[16], *be1 = (const float*)d_in[17];
    const float* g2 = (const float*)d_in[18], *be2 = (const float*)d_in[19];
    float* out = (float*)d_out;

    int N = in_sizes[1] / DD;   // 100000
    int E = in_sizes[2] / DD;   // 600000

    float *pQ, *pK, *pV, *pSK, *pAGG, *pH, *pDen;
    cudaGetSymbolAddress((void**)&pQ,   g_Q);
    cudaGetSymbolAddress((void**)&pK,   g_K);
    cudaGetSymbolAddress((void**)&pV,   g_V);
    cudaGetSymbolAddress((void**)&pSK,  g_SKIP);
    cudaGetSymbolAddress((void**)&pAGG, g_AGG);
    cudaGetSymbolAddress((void**)&pH,   g_H);
    cudaGetSymbolAddress((void**)&pDen, g_den);

    cudaFuncSetAttribute(proj_kernel, cudaFuncAttributeMaxDynamicSharedMemorySize,
                         GEMM_SMEM);
    cudaFuncSetAttribute(fused_edge_kernel, cudaFuncAttributeMaxDynamicSharedMemorySize,
                         FUSED_SMEM);
    cudaFuncSetAttribute(ffn_kernel, cudaFuncAttributeMaxDynamicSharedMemorySize,
                         FFN_SMEM);

    detect_idx_kernel<<<1, 32>>>((const long long*)eidx, E, N);

    // node projections (512 threads) + AGG/den zeroing
    int nb_node = (N + 63) / 64;
    proj_kernel<<<nb_node, 512, GEMM_SMEM>>>(x, N,
        Wq, Wk, Wv, Wskip, bq, bk, bv, bskip, pQ, pK, pV, pSK, pAGG, pDen);

    // fused edge GEMM + attention (512 threads, prefetch)
    int ntiles = (E + 63) / 64;
    int nb_fused = (ntiles + TPC - 1) / TPC;
    fused_edge_kernel<<<nb_fused, 512, FUSED_SMEM>>>(edge_attr, We, pQ, pK, pV,
                                                     eidx, E, pDen, pAGG);

    // fused: h = x + LN1(AGG/den + skip); out = h + LN2(FFN(h))
    ffn_kernel<<<nb_node, 512, FFN_SMEM>>>(x, pAGG, pSK, pDen, g1, be1, pH,
                                           W1, b1, W2, b2, g2, be2, out, N);
}